// round 12
// baseline (speedup 1.0000x reference)
#include <cuda_runtime.h>
#include <math.h>

#define T 2048
#define H 1024
#define NH 16
#define NKV 4
#define D 64
#define E 8
#define F 1024
#define QKV_N ((NH + 2*NKV) * D)   // 1536
#define EPS 1e-5f
#define ATT_SCALE 0.125f

// ---------------- scratch ---------------------------------------------------
__device__ float    g_h1[T * H];
__device__ float    g_qkv[T * QKV_N];
__device__ unsigned g_qT[NH * D * T];    // tf32 bits, [head][d][t]
__device__ unsigned g_kT[NKV * D * T];   // tf32 bits, [kvh][d][t]
__device__ unsigned g_vT[NKV * T * D];   // tf32 bits, [kvh][t][d]
__device__ float    g_ao[T * NH * D];
__device__ float    g_h2[T * H];
__device__ float    g_bufA[T * F];       // shared gate
__device__ float    g_bufB[T * F];       // shared up
__device__ float    g_bufC[T * F];       // routed gate (expert-grouped rows)
__device__ float    g_bufD[T * F];       // routed up
__device__ float    g_routed[T * H];     // routed expert output (dense by token)
__device__ float2   g_cs[T * 32];        // rope cos/sin table
__device__ int      g_eidx[T];
__device__ float    g_gate[T];
__device__ int      g_perm[T];
__device__ int      g_count[E];
__device__ int      g_base[E];

// ---------------- small utility kernels -------------------------------------
__global__ void rope_table_kernel(const int* __restrict__ pos) {
    int idx = blockIdx.x * blockDim.x + threadIdx.x;   // 0..65535
    if (idx < E) g_count[idx] = 0;
    int t = idx >> 5, i = idx & 31;
    float inv = powf(500000.0f, -((float)i) / 32.0f);
    float ang = (float)pos[t] * inv;
    float sn, cs;
    sincosf(ang, &sn, &cs);
    g_cs[idx] = make_float2(cs, sn);
}
__global__ void scan_scatter_kernel() {
    __shared__ int sbase[E];
    __shared__ int soffs[E];
    int tid = threadIdx.x;
    if (tid == 0) {
        int b = 0;
        for (int e = 0; e < E; e++) { sbase[e] = b; g_base[e] = b; b += g_count[e]; }
    }
    if (tid < E) soffs[tid] = 0;
    __syncthreads();
    for (int t = tid; t < T; t += 256) {
        int e = g_eidx[t];
        int p = sbase[e] + atomicAdd(&soffs[e], 1);
        g_perm[p] = t;
    }
}
__global__ void add_routed_kernel(float* __restrict__ out) {
    int i = blockIdx.x * blockDim.x + threadIdx.x;
    out[i] += g_routed[i];
}

// ---------------- rmsnorm (plain) -------------------------------------------
__global__ void rmsnorm_kernel(const float* __restrict__ in, const float* __restrict__ w,
                               float* __restrict__ out) {
    int row = blockIdx.x, tid = threadIdx.x;
    const float* p = in + (size_t)row * H;
    float v[4];
    float s = 0.f;
#pragma unroll
    for (int i = 0; i < 4; i++) { v[i] = p[tid + i * 256]; s += v[i] * v[i]; }
#pragma unroll
    for (int off = 16; off; off >>= 1) s += __shfl_xor_sync(0xffffffffu, s, off);
    __shared__ float sw[8];
    if ((tid & 31) == 0) sw[tid >> 5] = s;
    __syncthreads();
    __shared__ float stot;
    if (tid == 0) {
        float t2 = 0.f;
        for (int i = 0; i < 8; i++) t2 += sw[i];
        stot = t2;
    }
    __syncthreads();
    float r = rsqrtf(stot / (float)H + EPS);
    float* o = out + (size_t)row * H;
#pragma unroll
    for (int i = 0; i < 4; i++) o[tid + i * 256] = v[i] * r * w[tid + i * 256];
}

// ---------------- rmsnorm2 + router fused -----------------------------------
__global__ void rmsnorm_router_kernel(const float* __restrict__ in,
                                      const float* __restrict__ w,
                                      const float* __restrict__ rw,
                                      float* __restrict__ out) {
    int row = blockIdx.x, tid = threadIdx.x;
    const float* p = in + (size_t)row * H;
    float v[4];
    float s = 0.f;
#pragma unroll
    for (int i = 0; i < 4; i++) { v[i] = p[tid + i * 256]; s += v[i] * v[i]; }
#pragma unroll
    for (int off = 16; off; off >>= 1) s += __shfl_xor_sync(0xffffffffu, s, off);
    __shared__ float sw[8];
    if ((tid & 31) == 0) sw[tid >> 5] = s;
    __syncthreads();
    __shared__ float stot;
    if (tid == 0) {
        float t2 = 0.f;
        for (int i = 0; i < 8; i++) t2 += sw[i];
        stot = t2;
    }
    __syncthreads();
    float r = rsqrtf(stot / (float)H + EPS);
    float* o = out + (size_t)row * H;
    float acc[E] = {};
#pragma unroll
    for (int i = 0; i < 4; i++) {
        int h = tid + i * 256;
        float hv = v[i] * r * w[h];
        o[h] = hv;
        const float* rr = rw + (size_t)h * E;
#pragma unroll
        for (int e = 0; e < E; e++) acc[e] += hv * rr[e];
    }
#pragma unroll
    for (int e = 0; e < E; e++)
#pragma unroll
        for (int off = 16; off; off >>= 1)
            acc[e] += __shfl_xor_sync(0xffffffffu, acc[e], off);
    __shared__ float sred[8][E];
    int wp = tid >> 5, lane = tid & 31;
    if (lane == 0)
        for (int e = 0; e < E; e++) sred[wp][e] = acc[e];
    __syncthreads();
    if (tid == 0) {
        float best = -INFINITY;
        int bi = 0;
        for (int e = 0; e < E; e++) {
            float vv = 0.f;
            for (int ww = 0; ww < 8; ww++) vv += sred[ww][e];
            if (vv > best) { best = vv; bi = e; }
        }
        g_eidx[row] = bi;
        g_gate[row] = 1.f / (1.f + expf(-best));
        atomicAdd(&g_count[bi], 1);
    }
}

// =================== TF32 tensor-core machinery ==============================
__device__ __forceinline__ unsigned f2tf(float x) {
    unsigned r;
    asm("cvt.rna.tf32.f32 %0, %1;" : "=r"(r) : "f"(x));
    return r;
}
__device__ __forceinline__ void mma_tf32(float* c, const unsigned* a, const unsigned* b) {
    asm volatile(
        "mma.sync.aligned.m16n8k8.row.col.f32.tf32.tf32.f32 "
        "{%0,%1,%2,%3},{%4,%5,%6,%7},{%8,%9},{%0,%1,%2,%3};"
        : "+f"(c[0]), "+f"(c[1]), "+f"(c[2]), "+f"(c[3])
        : "r"(a[0]), "r"(a[1]), "r"(a[2]), "r"(a[3]), "r"(b[0]), "r"(b[1]));
}
__device__ __forceinline__ void cp16(unsigned smem_addr, const void* gptr) {
    asm volatile("cp.async.ca.shared.global [%0], [%1], 16;" :: "r"(smem_addr), "l"(gptr));
}
#define CP_COMMIT() asm volatile("cp.async.commit_group;")
#define CP_WAIT0()  asm volatile("cp.async.wait_group 0;")

#define KT 16
#define SMS 136

// 64x64 warp-tile mainloop: 4 warps, acc[4][8][4], 1.0 LDS/mma
#define MMA_TILE_COMPUTE64(Asb, Bsb)                                           \
    _Pragma("unroll")                                                          \
    for (int k8 = 0; k8 < KT; k8 += 8) {                                       \
        unsigned af[4][4], bf[8][2];                                           \
        _Pragma("unroll")                                                      \
        for (int mt = 0; mt < 4; mt++) {                                       \
            int mb = wm + mt * 16;                                             \
            af[mt][0] = Asb[(k8 + tg) * SMS + mb + g];                         \
            af[mt][1] = Asb[(k8 + tg) * SMS + mb + g + 8];                     \
            af[mt][2] = Asb[(k8 + tg + 4) * SMS + mb + g];                     \
            af[mt][3] = Asb[(k8 + tg + 4) * SMS + mb + g + 8];                 \
        }                                                                      \
        _Pragma("unroll")                                                      \
        for (int nt2 = 0; nt2 < 8; nt2++) {                                    \
            int nb = wn + nt2 * 8;                                             \
            bf[nt2][0] = Bsb[(k8 + tg) * SMS + nb + g];                        \
            bf[nt2][1] = Bsb[(k8 + tg + 4) * SMS + nb + g];                    \
        }                                                                      \
        _Pragma("unroll")                                                      \
        for (int mt = 0; mt < 4; mt++)                                         \
            _Pragma("unroll")                                                  \
            for (int nt2 = 0; nt2 < 8; nt2++)                                  \
                mma_tf32(acc[mt][nt2], af[mt], bf[nt2]);                       \
    }

// fills for 128-thread blocks: A thread = row tid, 16 k; B thread = k row tid>>3, 16 n
#define SILU1(x) ((x) / (1.f + __expf(-(x))))
#define FILL_A16(dst)                                                          \
    _Pragma("unroll")                                                          \
    for (int j = 0; j < 16; j++)                                               \
        (dst)[j * SMS + tid] = f2tf(((const float*)aV)[j] * ascale);
#define FILL_A16_SILU(dst)                                                     \
    _Pragma("unroll")                                                          \
    for (int j = 0; j < 16; j++)                                               \
        (dst)[j * SMS + tid] =                                                 \
            f2tf(SILU1(((const float*)gV)[j]) * ((const float*)uV)[j] * ascale);
#define FILL_B16(dst)                                                          \
    _Pragma("unroll")                                                          \
    for (int j = 0; j < 16; j++)                                               \
        (dst)[bk * SMS + bn + j] = f2tf(((const float*)bV)[j]);

// ---------------- dense tf32 GEMM (128 thr, 64x64 warp tiles) ---------------
__global__ __launch_bounds__(128)
void gemm_tf32(const float* __restrict__ A, const float* __restrict__ B,
               float* __restrict__ C, int M, int N, int K,
               const float* __restrict__ addsrc) {
    __shared__ unsigned As[2][KT * SMS];
    __shared__ unsigned Bs[2][KT * SMS];
    int tid = threadIdx.x;
    int warp = tid >> 5, lane = tid & 31;
    int g = lane >> 2, tg = lane & 3;
    int wm = (warp >> 1) * 64, wn = (warp & 1) * 64;
    int m0 = blockIdx.y * 128, n0 = blockIdx.x * 128;
    int bk = tid >> 3, bn = (tid & 7) * 16;
    const float* Ap = A + (size_t)(m0 + tid) * K;
    const float* Bp = B + (size_t)bk * N + n0 + bn;
    const float ascale = 1.f;
    float acc[4][8][4] = {};
    float4 aV[4], bV[4];

#pragma unroll
    for (int i = 0; i < 4; i++) aV[i] = *(const float4*)(Ap + i * 4);
#pragma unroll
    for (int i = 0; i < 4; i++) bV[i] = *(const float4*)(Bp + i * 4);
    FILL_A16(As[0]);
    FILL_B16(Bs[0]);
    __syncthreads();
    int nt = K / KT;
    int buf = 0;
    for (int kt = 0; kt < nt; kt++) {
        if (kt + 1 < nt) {
#pragma unroll
            for (int i = 0; i < 4; i++)
                aV[i] = *(const float4*)(Ap + (kt + 1) * KT + i * 4);
#pragma unroll
            for (int i = 0; i < 4; i++)
                bV[i] = *(const float4*)(Bp + (size_t)(kt + 1) * KT * N + i * 4);
        }
        const unsigned* Asb = As[buf];
        const unsigned* Bsb = Bs[buf];
        MMA_TILE_COMPUTE64(Asb, Bsb)
        if (kt + 1 < nt) {
            FILL_A16(As[buf ^ 1]);
            FILL_B16(Bs[buf ^ 1]);
        }
        __syncthreads();
        buf ^= 1;
    }
#pragma unroll
    for (int mt = 0; mt < 4; mt++) {
#pragma unroll
        for (int nt2 = 0; nt2 < 8; nt2++) {
            int r0 = m0 + wm + mt * 16 + g;
            int c = n0 + wn + nt2 * 8 + 2 * tg;
            float2 v0 = make_float2(acc[mt][nt2][0], acc[mt][nt2][1]);
            float2 v1 = make_float2(acc[mt][nt2][2], acc[mt][nt2][3]);
            if (addsrc) {
                float2 r = *(const float2*)(addsrc + (size_t)r0 * N + c);
                v0.x += r.x; v0.y += r.y;
                float2 r2 = *(const float2*)(addsrc + (size_t)(r0 + 8) * N + c);
                v1.x += r2.x; v1.y += r2.y;
            }
            *(float2*)(C + (size_t)r0 * N + c) = v0;
            *(float2*)(C + (size_t)(r0 + 8) * N + c) = v1;
        }
    }
}

// ------------- MoE up-projections mega-GEMM (z = 0..17) ---------------------
__global__ __launch_bounds__(128)
void moe_proj_tf32(const float* __restrict__ shg, const float* __restrict__ shu,
                   const float* __restrict__ wgate, const float* __restrict__ wup) {
    int z = blockIdx.z;
    int m0 = blockIdx.y * 128;
    int cnt, obase;
    const float* B;
    float* Cbuf;
    bool gathered;
    if (z < 2) {
        B = z ? shu : shg;
        Cbuf = z ? g_bufB : g_bufA;
        cnt = T; obase = 0; gathered = false;
    } else {
        int e = (z - 2) >> 1, kind = (z - 2) & 1;
        cnt = g_count[e];
        if (m0 >= cnt) return;
        B = (kind ? wup : wgate) + (size_t)e * H * F;
        Cbuf = kind ? g_bufD : g_bufC;
        obase = g_base[e]; gathered = true;
    }
    int n0 = blockIdx.x * 128;
    __shared__ unsigned As[2][KT * SMS];
    __shared__ unsigned Bs[2][KT * SMS];
    __shared__ int srcrow[128];
    int tid = threadIdx.x;
    {
        int mm = m0 + tid;
        srcrow[tid] = gathered ? ((mm < cnt) ? g_perm[obase + mm] : -1) : mm;
    }
    __syncthreads();
    int warp = tid >> 5, lane = tid & 31;
    int g = lane >> 2, tg = lane & 3;
    int wm = (warp >> 1) * 64, wn = (warp & 1) * 64;
    int bk = tid >> 3, bn = (tid & 7) * 16;
    int tok = srcrow[tid];
    const float ascale = gathered ? ((tok >= 0) ? g_gate[tok] : 0.f) : 1.f;
    const float* Ap = g_h2 + (size_t)((tok >= 0) ? tok : 0) * H;
    const float* Bp = B + (size_t)bk * F + n0 + bn;
    float acc[4][8][4] = {};
    float4 aV[4], bV[4];

#pragma unroll
    for (int i = 0; i < 4; i++) aV[i] = *(const float4*)(Ap + i * 4);
#pragma unroll
    for (int i = 0; i < 4; i++) bV[i] = *(const float4*)(Bp + i * 4);
    FILL_A16(As[0]);
    FILL_B16(Bs[0]);
    __syncthreads();
    int nt = H / KT;
    int buf = 0;
    for (int kt = 0; kt < nt; kt++) {
        if (kt + 1 < nt) {
#pragma unroll
            for (int i = 0; i < 4; i++)
                aV[i] = *(const float4*)(Ap + (kt + 1) * KT + i * 4);
#pragma unroll
            for (int i = 0; i < 4; i++)
                bV[i] = *(const float4*)(Bp + (size_t)(kt + 1) * KT * F + i * 4);
        }
        const unsigned* Asb = As[buf];
        const unsigned* Bsb = Bs[buf];
        MMA_TILE_COMPUTE64(Asb, Bsb)
        if (kt + 1 < nt) {
            FILL_A16(As[buf ^ 1]);
            FILL_B16(Bs[buf ^ 1]);
        }
        __syncthreads();
        buf ^= 1;
    }
#pragma unroll
    for (int mt = 0; mt < 4; mt++) {
#pragma unroll
        for (int nt2 = 0; nt2 < 8; nt2++) {
            int mi0 = wm + mt * 16 + g;
            int c = n0 + wn + nt2 * 8 + 2 * tg;
            if (m0 + mi0 < cnt)
                *(float2*)(Cbuf + (size_t)(obase + m0 + mi0) * F + c) =
                    make_float2(acc[mt][nt2][0], acc[mt][nt2][1]);
            if (m0 + mi0 + 8 < cnt)
                *(float2*)(Cbuf + (size_t)(obase + m0 + mi0 + 8) * F + c) =
                    make_float2(acc[mt][nt2][2], acc[mt][nt2][3]);
        }
    }
}

// ------------- MoE down-projections mega-GEMM (z = 0..8), silu fused --------
__global__ __launch_bounds__(128)
void moe_down_tf32(const float* __restrict__ shd, const float* __restrict__ wdown,
                   float* __restrict__ out) {
    int z = blockIdx.z;
    int m0 = blockIdx.y * 128;
    int cnt, abase;
    const float* B;
    const float* Agate;
    const float* Aup;
    float* Dst;
    if (z == 0) {
        cnt = T; abase = 0;
        B = shd; Agate = g_bufA; Aup = g_bufB; Dst = out;
    } else {
        int e = z - 1;
        cnt = g_count[e];
        if (m0 >= cnt) return;
        abase = g_base[e];
        B = wdown + (size_t)e * F * H;
        Agate = g_bufC; Aup = g_bufD; Dst = g_routed;
    }
    int n0 = blockIdx.x * 128;
    __shared__ unsigned As[2][KT * SMS];
    __shared__ unsigned Bs[2][KT * SMS];
    __shared__ int rtok[128];
    int tid = threadIdx.x;
    {
        int mm = m0 + tid;
        rtok[tid] = (z == 0) ? mm : ((mm < cnt) ? g_perm[abase + mm] : -1);
    }
    __syncthreads();
    int warp = tid >> 5, lane = tid & 31;
    int g = lane >> 2, tg = lane & 3;
    int wm = (warp >> 1) * 64, wn = (warp & 1) * 64;
    int bk = tid >> 3, bn = (tid & 7) * 16;
    bool arow_ok = (m0 + tid) < cnt;
    const float ascale = arow_ok ? 1.f : 0.f;
    size_t aoff = (size_t)(abase + (arow_ok ? (m0 + tid) : 0)) * F;
    const float* Apg = Agate + aoff;
    const float* Apu = Aup + aoff;
    const float* Bp = B + (size_t)bk * H + n0 + bn;
    float acc[4][8][4] = {};
    float4 gV[4], uV[4], bV[4];

#pragma unroll
    for (int i = 0; i < 4; i++) gV[i] = *(const float4*)(Apg + i * 4);
#pragma unroll
    for (int i = 0; i < 4; i++) uV[i] = *(const float4*)(Apu + i * 4);
#pragma unroll
    for (int i = 0; i < 4; i++) bV[i] = *(const float4*)(Bp + i * 4);
    FILL_A16_SILU(As[0]);
    FILL_B16(Bs[0]);
    __syncthreads();
    int nt = F / KT;
    int buf = 0;
    for (int kt = 0; kt < nt; kt++) {
        if (kt + 1 < nt) {
#pragma unroll
            for (int i = 0; i < 4; i++)
                gV[i] = *(const float4*)(Apg + (kt + 1) * KT + i * 4);
#pragma unroll
            for (int i = 0; i < 4; i++)
                uV[i] = *(const float4*)(Apu + (kt + 1) * KT + i * 4);
#pragma unroll
            for (int i = 0; i < 4; i++)
                bV[i] = *(const float4*)(Bp + (size_t)(kt + 1) * KT * H + i * 4);
        }
        const unsigned* Asb = As[buf];
        const unsigned* Bsb = Bs[buf];
        MMA_TILE_COMPUTE64(Asb, Bsb)
        if (kt + 1 < nt) {
            FILL_A16_SILU(As[buf ^ 1]);
            FILL_B16(Bs[buf ^ 1]);
        }
        __syncthreads();
        buf ^= 1;
    }
#pragma unroll
    for (int mt = 0; mt < 4; mt++) {
#pragma unroll
        for (int nt2 = 0; nt2 < 8; nt2++) {
            int mi0 = wm + mt * 16 + g;
            int c = n0 + wn + nt2 * 8 + 2 * tg;
            if (m0 + mi0 < cnt) {
                int t = rtok[mi0];
                *(float2*)(Dst + (size_t)t * H + c) =
                    make_float2(acc[mt][nt2][0], acc[mt][nt2][1]);
            }
            if (m0 + mi0 + 8 < cnt) {
                int t = rtok[mi0 + 8];
                *(float2*)(Dst + (size_t)t * H + c) =
                    make_float2(acc[mt][nt2][2], acc[mt][nt2][3]);
            }
        }
    }
}

// ---------------- rope + rms + COALESCED transpose --------------------------
__global__ void rope_rms_kernel() {
    int t0 = blockIdx.x * 32;
    int h = blockIdx.y;
    int tid = threadIdx.x;
    if (h >= NH + NKV) {
        int kh = h - NH - NKV;
        const float* src = g_qkv + NH * D + NKV * D + kh * D;
#pragma unroll
        for (int i = 0; i < 8; i++) {
            int e = tid + i * 256;
            int tl = e >> 6, d = e & 63;
            float v = src[(size_t)(t0 + tl) * QKV_N + d];
            g_vT[((size_t)kh * T + t0 + tl) * D + d] = f2tf(v);
        }
        return;
    }
    const float* src;
    unsigned* dstT;
    if (h < NH) {
        src = g_qkv + h * D;
        dstT = g_qT + (size_t)h * D * T;
    } else {
        src = g_qkv + NH * D + (h - NH) * D;
        dstT = g_kT + (size_t)(h - NH) * D * T;
    }
    __shared__ float rows[32][65];
    __shared__ float psum[32][8];
#pragma unroll
    for (int i = 0; i < 8; i++) {
        int e = tid + i * 256;
        int tl = e >> 6, d = e & 63;
        rows[tl][d] = src[(size_t)(t0 + tl) * QKV_N + d];
    }
    __syncthreads();
    int tl = tid >> 3;
    int dbase = (tid & 7) * 8;
    float vals[8];
    float sq = 0.f;
#pragma unroll
    for (int j = 0; j < 8; j++) {
        int d = dbase + j;
        int i = d & 31;
        float2 cspair = g_cs[(t0 + tl) * 32 + i];
        float x1 = rows[tl][i], x2 = rows[tl][i + 32];
        float val = (d < 32) ? (x1 * cspair.x - x2 * cspair.y)
                             : (x2 * cspair.x + x1 * cspair.y);
        vals[j] = val;
        sq += val * val;
    }
    psum[tl][tid & 7] = sq;
    __syncthreads();
    float tot = 0.f;
#pragma unroll
    for (int k = 0; k < 8; k++) tot += psum[tl][k];
    float r = rsqrtf(tot / (float)D + EPS);
#pragma unroll
    for (int j = 0; j < 8; j++) rows[tl][dbase + j] = vals[j] * r;
    __syncthreads();
#pragma unroll
    for (int i = 0; i < 8; i++) {
        int e = tid + i * 256;
        int d = e >> 5, tcol = e & 31;
        dstT[(size_t)d * T + t0 + tcol] = f2tf(rows[tcol][d]);
    }
}

// ================= tensor-core flash attention (cp.async pipelined) ==========
#define AS 72
__global__ __launch_bounds__(128)
void attn_tc() {
    extern __shared__ unsigned usmem[];
    unsigned* Ks0 = usmem;
    unsigned* Ks1 = usmem + 64 * AS;
    unsigned* Vs0 = usmem + 2 * 64 * AS;
    unsigned* Vs1 = usmem + 3 * 64 * AS;
    unsigned* Ps  = usmem + 4 * 64 * AS;
    int qt = (int)gridDim.x - 1 - (int)blockIdx.x;
    int head = blockIdx.y;
    int kvh = head >> 2;
    int tid = threadIdx.x, warp = tid >> 5, lane = tid & 31;
    int g = lane >> 2, tg = lane & 3;
    int q0 = qt * 64;
    int wq = warp * 16;

    const unsigned* ksrc = g_kT + (size_t)kvh * D * T;
    const unsigned* vsrc = g_vT + (size_t)kvh * T * D;

    {
        const unsigned* qsrc = g_qT + (size_t)head * D * T + q0;
        for (int e4 = tid; e4 < 64 * 16; e4 += 128) {
            int d = e4 >> 4, r4 = (e4 & 15) * 4;
            uint4 v = *(const uint4*)(qsrc + (size_t)d * T + r4);
            *(uint4*)&Ks0[d * AS + r4] = v;
        }
    }
    __syncthreads();
    unsigned qf[8][4];
#pragma unroll
    for (int kc = 0; kc < 8; kc++) {
        qf[kc][0] = Ks0[(kc * 8 + tg) * AS + wq + g];
        qf[kc][1] = Ks0[(kc * 8 + tg) * AS + wq + g + 8];
        qf[kc][2] = Ks0[(kc * 8 + tg + 4) * AS + wq + g];
        qf[kc][3] = Ks0[(kc * 8 + tg + 4) * AS + wq + g + 8];
    }
    __syncthreads();

    int r0 = q0 + wq + g, r1 = r0 + 8;
    float m0 = -INFINITY, m1 = -INFINITY, l0 = 0.f, l1 = 0.f;
    float accO[8][4] = {};

    {
        for (int e4 = tid; e4 < 64 * 16; e4 += 128) {
            int d = e4 >> 4, c4 = (e4 & 15) * 4;
            cp16((unsigned)__cvta_generic_to_shared(&Ks0[d * AS + c4]),
                 ksrc + (size_t)d * T + c4);
        }
        for (int e4 = tid; e4 < 64 * 16; e4 += 128) {
            int c = e4 >> 4, d4 = (e4 & 15) * 4;
            cp16((unsigned)__cvta_generic_to_shared(&Vs0[c * AS + d4]),
                 vsrc + (size_t)c * D + d4);
        }
        CP_COMMIT();
    }

    int buf = 0;
    for (int j0 = 0; j0 <= qt; j0++) {
        int k0 = j0 * 64;
        CP_WAIT0();
        __syncthreads();
        if (j0 < qt) {
            unsigned* Kn = buf ? Ks0 : Ks1;
            unsigned* Vn = buf ? Vs0 : Vs1;
            int kn = k0 + 64;
            for (int e4 = tid; e4 < 64 * 16; e4 += 128) {
                int d = e4 >> 4, c4 = (e4 & 15) * 4;
                cp16((unsigned)__cvta_generic_to_shared(&Kn[d * AS + c4]),
                     ksrc + (size_t)d * T + kn + c4);
            }
            for (int e4 = tid; e4 < 64 * 16; e4 += 128) {
                int c = e4 >> 4, d4 = (e4 & 15) * 4;
                cp16((unsigned)__cvta_generic_to_shared(&Vn[c * AS + d4]),
                     vsrc + (size_t)(kn + c) * D + d4);
            }
            CP_COMMIT();
        }
        const unsigned* Kb = buf ? Ks1 : Ks0;
        const unsigned* Vb = buf ? Vs1 : Vs0;
        float sc[8][4] = {};
#pragma unroll
        for (int kc = 0; kc < 8; kc++) {
            unsigned bfr[8][2];
#pragma unroll
            for (int n = 0; n < 8; n++) {
                bfr[n][0] = Kb[(kc * 8 + tg) * AS + n * 8 + g];
                bfr[n][1] = Kb[(kc * 8 + tg + 4) * AS + n * 8 + g];
            }
#pragma unroll
            for (int n = 0; n < 8; n++) mma_tf32(sc[n], qf[kc], bfr[n]);
        }
        float mx0 = -INFINITY, mx1 = -INFINITY;
#pragma unroll
        for (int n = 0; n < 8; n++) {
            int c0 = k0 + n * 8 + 2 * tg;
            float s0 = (c0 <= r0) ? sc[n][0] * ATT_SCALE : -INFINITY;
            float s1 = (c0 + 1 <= r0) ? sc[n][1] * ATT_SCALE : -INFINITY;
            float s2 = (c0 <= r1) ? sc[n][2] * ATT_SCALE : -INFINITY;
            float s3 = (c0 + 1 <= r1) ? sc[n][3] * ATT_SCALE : -INFINITY;
            sc[n][0] = s0; sc[n][1] = s1; sc[n][2] = s2; sc[n][3] = s3;
            mx0 = fmaxf(mx0, fmaxf(s0, s1));
            mx1 = fmaxf(mx1, fmaxf(s2, s3));
        }
        mx0 = fmaxf(mx0, __shfl_xor_sync(0xffffffffu, mx0, 1));
        mx0 = fmaxf(mx0, __shfl_xor_sync(0xffffffffu, mx0, 2));
        mx1 = fmaxf(mx1, __shfl_xor_sync(0xffffffffu, mx1, 1));
        mx1 = fmaxf(mx1, __shfl_xor_sync(0xffffffffu, mx1, 2));
        float nm0 = fmaxf(m0, mx0), nm1 = fmaxf(m1, mx1);
        float corr0 = __expf(m0 - nm0), corr1 = __expf(m1 - nm1);
        m0 = nm0; m1 = nm1;
        float rs0 = 0.f, rs1 = 0.f;
#pragma unroll
        for (int n = 0; n < 8; n++) {
            int cl = n * 8 + 2 * tg;
            float p0 = __expf(sc[n][0] - nm0);
            float p1 = __expf(sc[n][1] - nm0);
            float p2 = __expf(sc[n][2] - nm1);
            float p3 = __expf(sc[n][3] - nm1);
            rs0 += p0 + p1; rs1 += p2 + p3;
            Ps[cl * AS + wq + g] = f2tf(p0);
            Ps[(cl + 1) * AS + wq + g] = f2tf(p1);
            Ps[cl * AS + wq + g + 8] = f2tf(p2);
            Ps[(cl + 1) * AS + wq + g + 8] = f2tf(p3);
        }
        rs0 += __shfl_xor_sync(0xffffffffu, rs0, 1);
        rs0 += __shfl_xor_sync(0xffffffffu, rs0, 2);
        rs1 += __shfl_xor_sync(0xffffffffu, rs1, 1);
        rs1 += __shfl_xor_sync(0xffffffffu, rs1, 2);
        l0 = l0 * corr0 + rs0;
        l1 = l1 * corr1 + rs1;
#pragma unroll
        for (int n = 0; n < 8; n++) {
            accO[n][0] *= corr0; accO[n][1] *= corr0;
            accO[n][2] *= corr1; accO[n][3] *= corr1;
        }
        __syncwarp();
#pragma unroll
        for (int kc = 0; kc < 8; kc++) {
            unsigned af[4];
            af[0] = Ps[(kc * 8 + tg) * AS + wq + g];
            af[1] = Ps[(kc * 8 + tg) * AS + wq + g + 8];
            af[2] = Ps[(kc * 8 + tg + 4) * AS + wq + g];
            af[3] = Ps[(kc * 8 + tg + 4) * AS + wq + g + 8];
#pragma unroll
            for (int n = 0; n < 8; n++) {
                unsigned bfr2[2];
                bfr2[0] = Vb[(kc * 8 + tg) * AS + n * 8 + g];
                bfr2[1] = Vb[(kc * 8 + tg + 4) * AS + n * 8 + g];
                mma_tf32(accO[n], af, bfr2);
            }
        }
        buf ^= 1;
    }
    float inv0 = 1.f / l0, inv1 = 1.f / l1;
#pragma unroll
    for (int n = 0; n < 8; n++) {
        int c = head * D + n * 8 + 2 * tg;
        *(float2*)&g_ao[(size_t)r0 * (NH * D) + c] =
            make_float2(accO[n][0] * inv0, accO[n][1] * inv0);
        *(float2*)&g_ao[(size_t)r1 * (NH * D) + c] =
            make_float2(accO[n][2] * inv1, accO[n][3] * inv1);
    }
}

// ---------------- launch ------------------------------------------------------
extern "C" void kernel_launch(void* const* d_in, const int* in_sizes, int n_in,
                              void* d_out, int out_size) {
    const int* pos = (const int*)d_in[0];
    const float* hidden = (const float*)d_in[1];
    const float* ln1 = (const float*)d_in[2];
    const float* ln2 = (const float*)d_in[3];
    const float* wqkv = (const float*)d_in[4];
    const float* wo = (const float*)d_in[5];
    const float* rw = (const float*)d_in[6];
    const float* wgate = (const float*)d_in[7];
    const float* wup = (const float*)d_in[8];
    const float* wdown = (const float*)d_in[9];
    const float* shg = (const float*)d_in[10];
    const float* shu = (const float*)d_in[11];
    const float* shd = (const float*)d_in[12];
    float* out = (float*)d_out;
    float* resid = out + (size_t)T * H;

    float *p_h1, *p_h2, *p_qkv, *p_ao;
    cudaGetSymbolAddress((void**)&p_h1, g_h1);
    cudaGetSymbolAddress((void**)&p_h2, g_h2);
    cudaGetSymbolAddress((void**)&p_qkv, g_qkv);
    cudaGetSymbolAddress((void**)&p_ao, g_ao);

    static int attn_smem_set = 0;
    const int ATTN_SMEM = 5 * 64 * AS * 4;   // 92160 B
    if (!attn_smem_set) {
        cudaFuncSetAttribute(attn_tc, cudaFuncAttributeMaxDynamicSharedMemorySize, ATTN_SMEM);
        attn_smem_set = 1;
    }

    rope_table_kernel<<<256, 256>>>(pos);   // also zeroes g_count
    rmsnorm_kernel<<<T, 256>>>(hidden, ln1, p_h1);
    gemm_tf32<<<dim3(QKV_N / 128, T / 128), 128>>>(p_h1, wqkv, p_qkv, T, QKV_N, H, nullptr);
    rope_rms_kernel<<<dim3(T / 32, NH + 2 * NKV), 256>>>();
    attn_tc<<<dim3(T / 64, NH), 128, ATTN_SMEM>>>();
    gemm_tf32<<<dim3(H / 128, T / 128), 128>>>(p_ao, wo, resid, T, H, NH * D, hidden);
    rmsnorm_router_kernel<<<T, 256>>>(resid, ln2, rw, p_h2);
    scan_scatter_kernel<<<1, 256>>>();
    moe_proj_tf32<<<dim3(F / 128, T / 128, 2 + 2 * E), 128>>>(shg, shu, wgate, wup);
    moe_down_tf32<<<dim3(H / 128, T / 128, 1 + E), 128>>>(shd, wdown, out);
    add_routed_kernel<<<(T * H) / 256, 256>>>(out);
    (void)in_sizes; (void)n_in; (void)out_size;
}

// round 13
// speedup vs baseline: 1.1920x; 1.1920x over previous
#include <cuda_runtime.h>
#include <math.h>

#define T 2048
#define H 1024
#define NH 16
#define NKV 4
#define D 64
#define E 8
#define F 1024
#define QKV_N ((NH + 2*NKV) * D)   // 1536
#define EPS 1e-5f
#define ATT_SCALE 0.125f

// ---------------- scratch ---------------------------------------------------
__device__ float    g_h1[T * H];
__device__ float    g_qkv[T * QKV_N];
__device__ unsigned g_qT[NH * D * T];    // tf32 bits, [head][d][t]
__device__ unsigned g_kT[NKV * D * T];   // tf32 bits, [kvh][d][t]
__device__ unsigned g_vT[NKV * T * D];   // tf32 bits, [kvh][t][d]
__device__ float    g_ao[T * NH * D];
__device__ float    g_h2[T * H];
__device__ float    g_bufA[T * F];
__device__ float    g_bufB[T * F];
__device__ float    g_bufC[T * F];
__device__ float    g_bufD[T * F];
__device__ float    g_routed[T * H];
__device__ float2   g_cs[T * 32];
__device__ int      g_eidx[T];
__device__ float    g_gate[T];
__device__ int      g_perm[T];
__device__ int      g_count[E];
__device__ int      g_base[E];

// ---------------- small utility kernels -------------------------------------
__global__ void rope_table_kernel(const int* __restrict__ pos) {
    int idx = blockIdx.x * blockDim.x + threadIdx.x;
    if (idx < E) g_count[idx] = 0;
    int t = idx >> 5, i = idx & 31;
    float inv = powf(500000.0f, -((float)i) / 32.0f);
    float ang = (float)pos[t] * inv;
    float sn, cs;
    sincosf(ang, &sn, &cs);
    g_cs[idx] = make_float2(cs, sn);
}
__global__ void scan_scatter_kernel() {
    __shared__ int sbase[E];
    __shared__ int soffs[E];
    int tid = threadIdx.x;
    if (tid == 0) {
        int b = 0;
        for (int e = 0; e < E; e++) { sbase[e] = b; g_base[e] = b; b += g_count[e]; }
    }
    if (tid < E) soffs[tid] = 0;
    __syncthreads();
    for (int t = tid; t < T; t += 256) {
        int e = g_eidx[t];
        int p = sbase[e] + atomicAdd(&soffs[e], 1);
        g_perm[p] = t;
    }
}
__global__ void add_routed_kernel(float* __restrict__ out) {
    int i = blockIdx.x * blockDim.x + threadIdx.x;
    float4 a = *(const float4*)(out + i * 4);
    float4 b = *(const float4*)(g_routed + i * 4);
    a.x += b.x; a.y += b.y; a.z += b.z; a.w += b.w;
    *(float4*)(out + i * 4) = a;
}

// ---------------- rmsnorm (plain) -------------------------------------------
__global__ void rmsnorm_kernel(const float* __restrict__ in, const float* __restrict__ w,
                               float* __restrict__ out) {
    int row = blockIdx.x, tid = threadIdx.x;
    const float* p = in + (size_t)row * H;
    float v[4];
    float s = 0.f;
#pragma unroll
    for (int i = 0; i < 4; i++) { v[i] = p[tid + i * 256]; s += v[i] * v[i]; }
#pragma unroll
    for (int off = 16; off; off >>= 1) s += __shfl_xor_sync(0xffffffffu, s, off);
    __shared__ float sw[8];
    if ((tid & 31) == 0) sw[tid >> 5] = s;
    __syncthreads();
    __shared__ float stot;
    if (tid == 0) {
        float t2 = 0.f;
        for (int i = 0; i < 8; i++) t2 += sw[i];
        stot = t2;
    }
    __syncthreads();
    float r = rsqrtf(stot / (float)H + EPS);
    float* o = out + (size_t)row * H;
#pragma unroll
    for (int i = 0; i < 4; i++) o[tid + i * 256] = v[i] * r * w[tid + i * 256];
}

// ---------------- rmsnorm2 + router fused -----------------------------------
__global__ void rmsnorm_router_kernel(const float* __restrict__ in,
                                      const float* __restrict__ w,
                                      const float* __restrict__ rw,
                                      float* __restrict__ out) {
    int row = blockIdx.x, tid = threadIdx.x;
    const float* p = in + (size_t)row * H;
    float v[4];
    float s = 0.f;
#pragma unroll
    for (int i = 0; i < 4; i++) { v[i] = p[tid + i * 256]; s += v[i] * v[i]; }
#pragma unroll
    for (int off = 16; off; off >>= 1) s += __shfl_xor_sync(0xffffffffu, s, off);
    __shared__ float sw[8];
    if ((tid & 31) == 0) sw[tid >> 5] = s;
    __syncthreads();
    __shared__ float stot;
    if (tid == 0) {
        float t2 = 0.f;
        for (int i = 0; i < 8; i++) t2 += sw[i];
        stot = t2;
    }
    __syncthreads();
    float r = rsqrtf(stot / (float)H + EPS);
    float* o = out + (size_t)row * H;
    float acc[E] = {};
#pragma unroll
    for (int i = 0; i < 4; i++) {
        int h = tid + i * 256;
        float hv = v[i] * r * w[h];
        o[h] = hv;
        const float* rr = rw + (size_t)h * E;
#pragma unroll
        for (int e = 0; e < E; e++) acc[e] += hv * rr[e];
    }
#pragma unroll
    for (int e = 0; e < E; e++)
#pragma unroll
        for (int off = 16; off; off >>= 1)
            acc[e] += __shfl_xor_sync(0xffffffffu, acc[e], off);
    __shared__ float sred[8][E];
    int wp = tid >> 5, lane = tid & 31;
    if (lane == 0)
        for (int e = 0; e < E; e++) sred[wp][e] = acc[e];
    __syncthreads();
    if (tid == 0) {
        float best = -INFINITY;
        int bi = 0;
        for (int e = 0; e < E; e++) {
            float vv = 0.f;
            for (int ww = 0; ww < 8; ww++) vv += sred[ww][e];
            if (vv > best) { best = vv; bi = e; }
        }
        g_eidx[row] = bi;
        g_gate[row] = 1.f / (1.f + expf(-best));
        atomicAdd(&g_count[bi], 1);
    }
}

// =================== TF32 tensor-core machinery ==============================
__device__ __forceinline__ unsigned f2tf(float x) {
    unsigned r;
    asm("cvt.rna.tf32.f32 %0, %1;" : "=r"(r) : "f"(x));
    return r;
}
__device__ __forceinline__ void mma_tf32(float* c, const unsigned* a, const unsigned* b) {
    asm volatile(
        "mma.sync.aligned.m16n8k8.row.col.f32.tf32.tf32.f32 "
        "{%0,%1,%2,%3},{%4,%5,%6,%7},{%8,%9},{%0,%1,%2,%3};"
        : "+f"(c[0]), "+f"(c[1]), "+f"(c[2]), "+f"(c[3])
        : "r"(a[0]), "r"(a[1]), "r"(a[2]), "r"(a[3]), "r"(b[0]), "r"(b[1]));
}
__device__ __forceinline__ void cp16(unsigned smem_addr, const void* gptr) {
    asm volatile("cp.async.ca.shared.global [%0], [%1], 16;" :: "r"(smem_addr), "l"(gptr));
}
#define CP_COMMIT() asm volatile("cp.async.commit_group;")
#define CP_WAIT0()  asm volatile("cp.async.wait_group 0;")

#define KT 16
#define SMS 136

// R11-proven 64x32 warp-tile mainloop (8 warps, acc 64 regs)
#define MMA_TILE_COMPUTE(Asb, Bsb)                                             \
    _Pragma("unroll")                                                          \
    for (int k8 = 0; k8 < KT; k8 += 8) {                                       \
        unsigned af[4][4], bf[4][2];                                           \
        _Pragma("unroll")                                                      \
        for (int mt = 0; mt < 4; mt++) {                                       \
            int mb = wm + mt * 16;                                             \
            af[mt][0] = Asb[(k8 + tg) * SMS + mb + g];                         \
            af[mt][1] = Asb[(k8 + tg) * SMS + mb + g + 8];                     \
            af[mt][2] = Asb[(k8 + tg + 4) * SMS + mb + g];                     \
            af[mt][3] = Asb[(k8 + tg + 4) * SMS + mb + g + 8];                 \
        }                                                                      \
        _Pragma("unroll")                                                      \
        for (int nt2 = 0; nt2 < 4; nt2++) {                                    \
            int nb = wn + nt2 * 8;                                             \
            bf[nt2][0] = Bsb[(k8 + tg) * SMS + nb + g];                        \
            bf[nt2][1] = Bsb[(k8 + tg + 4) * SMS + nb + g];                    \
        }                                                                      \
        _Pragma("unroll")                                                      \
        for (int mt = 0; mt < 4; mt++)                                         \
            _Pragma("unroll")                                                  \
            for (int nt2 = 0; nt2 < 4; nt2++)                                  \
                mma_tf32(acc[mt][nt2], af[mt], bf[nt2]);                       \
    }

#define FILL_A(dst, v0, v1, scale)                                             \
    do {                                                                       \
        (dst)[(acol + 0) * SMS + arow] = f2tf((v0).x * (scale));               \
        (dst)[(acol + 1) * SMS + arow] = f2tf((v0).y * (scale));               \
        (dst)[(acol + 2) * SMS + arow] = f2tf((v0).z * (scale));               \
        (dst)[(acol + 3) * SMS + arow] = f2tf((v0).w * (scale));               \
        (dst)[(acol + 4) * SMS + arow] = f2tf((v1).x * (scale));               \
        (dst)[(acol + 5) * SMS + arow] = f2tf((v1).y * (scale));               \
        (dst)[(acol + 6) * SMS + arow] = f2tf((v1).z * (scale));               \
        (dst)[(acol + 7) * SMS + arow] = f2tf((v1).w * (scale));               \
    } while (0)

#define SILU1(x) ((x) / (1.f + __expf(-(x))))
#define FILL_A_SILU(dst, gv0, gv1, uv0, uv1, mask)                             \
    do {                                                                       \
        (dst)[(acol + 0) * SMS + arow] = f2tf(SILU1((gv0).x) * (uv0).x * (mask)); \
        (dst)[(acol + 1) * SMS + arow] = f2tf(SILU1((gv0).y) * (uv0).y * (mask)); \
        (dst)[(acol + 2) * SMS + arow] = f2tf(SILU1((gv0).z) * (uv0).z * (mask)); \
        (dst)[(acol + 3) * SMS + arow] = f2tf(SILU1((gv0).w) * (uv0).w * (mask)); \
        (dst)[(acol + 4) * SMS + arow] = f2tf(SILU1((gv1).x) * (uv1).x * (mask)); \
        (dst)[(acol + 5) * SMS + arow] = f2tf(SILU1((gv1).y) * (uv1).y * (mask)); \
        (dst)[(acol + 6) * SMS + arow] = f2tf(SILU1((gv1).z) * (uv1).z * (mask)); \
        (dst)[(acol + 7) * SMS + arow] = f2tf(SILU1((gv1).w) * (uv1).w * (mask)); \
    } while (0)

#define FILL_B(dst, v0, v1)                                                    \
    do {                                                                       \
        unsigned* bd_ = (dst) + bk * SMS + bn;                                 \
        bd_[0] = f2tf((v0).x); bd_[1] = f2tf((v0).y);                          \
        bd_[2] = f2tf((v0).z); bd_[3] = f2tf((v0).w);                          \
        bd_[4] = f2tf((v1).x); bd_[5] = f2tf((v1).y);                          \
        bd_[6] = f2tf((v1).z); bd_[7] = f2tf((v1).w);                          \
    } while (0)

// ---------------- dense tf32 GEMM (R11 config) -------------------------------
__global__ __launch_bounds__(256)
void gemm_tf32(const float* __restrict__ A, const float* __restrict__ B,
               float* __restrict__ C, int M, int N, int K,
               const float* __restrict__ addsrc) {
    __shared__ unsigned As[2][KT * SMS];
    __shared__ unsigned Bs[2][KT * SMS];
    int tid = threadIdx.x;
    int warp = tid >> 5, lane = tid & 31;
    int g = lane >> 2, tg = lane & 3;
    int wm = (warp >> 2) * 64, wn = (warp & 3) * 32;
    int m0 = blockIdx.y * 128, n0 = blockIdx.x * 128;
    int arow = tid >> 1, acol = (tid & 1) * 8;
    int bk = tid >> 4, bn = (tid & 15) * 8;
    const float* Ap = A + (size_t)(m0 + arow) * K + acol;
    const float* Bp = B + (size_t)bk * N + n0 + bn;
    float acc[4][4][4] = {};

    float4 av0 = *(const float4*)Ap, av1 = *(const float4*)(Ap + 4);
    float4 bv0 = *(const float4*)Bp, bv1 = *(const float4*)(Bp + 4);
    FILL_A(As[0], av0, av1, 1.f);
    FILL_B(Bs[0], bv0, bv1);
    __syncthreads();
    int nt = K / KT;
    int buf = 0;
    for (int kt = 0; kt < nt; kt++) {
        if (kt + 1 < nt) {
            av0 = *(const float4*)(Ap + (kt + 1) * KT);
            av1 = *(const float4*)(Ap + (kt + 1) * KT + 4);
            bv0 = *(const float4*)(Bp + (size_t)(kt + 1) * KT * N);
            bv1 = *(const float4*)(Bp + (size_t)(kt + 1) * KT * N + 4);
        }
        const unsigned* Asb = As[buf];
        const unsigned* Bsb = Bs[buf];
        MMA_TILE_COMPUTE(Asb, Bsb)
        if (kt + 1 < nt) {
            FILL_A(As[buf ^ 1], av0, av1, 1.f);
            FILL_B(Bs[buf ^ 1], bv0, bv1);
        }
        __syncthreads();
        buf ^= 1;
    }
#pragma unroll
    for (int mt = 0; mt < 4; mt++) {
#pragma unroll
        for (int nt2 = 0; nt2 < 4; nt2++) {
            int r0 = m0 + wm + mt * 16 + g;
            int c = n0 + wn + nt2 * 8 + 2 * tg;
            float2 v0 = make_float2(acc[mt][nt2][0], acc[mt][nt2][1]);
            float2 v1 = make_float2(acc[mt][nt2][2], acc[mt][nt2][3]);
            if (addsrc) {
                float2 r = *(const float2*)(addsrc + (size_t)r0 * N + c);
                v0.x += r.x; v0.y += r.y;
                float2 r2 = *(const float2*)(addsrc + (size_t)(r0 + 8) * N + c);
                v1.x += r2.x; v1.y += r2.y;
            }
            *(float2*)(C + (size_t)r0 * N + c) = v0;
            *(float2*)(C + (size_t)(r0 + 8) * N + c) = v1;
        }
    }
}

// ------------- MoE up-projections mega-GEMM (z = 0..17, R11 config) ---------
__global__ __launch_bounds__(256)
void moe_proj_tf32(const float* __restrict__ shg, const float* __restrict__ shu,
                   const float* __restrict__ wgate, const float* __restrict__ wup) {
    int z = blockIdx.z;
    int m0 = blockIdx.y * 128;
    int cnt, obase;
    const float* B;
    float* Cbuf;
    bool gathered;
    if (z < 2) {
        B = z ? shu : shg;
        Cbuf = z ? g_bufB : g_bufA;
        cnt = T; obase = 0; gathered = false;
    } else {
        int e = (z - 2) >> 1, kind = (z - 2) & 1;
        cnt = g_count[e];
        if (m0 >= cnt) return;
        B = (kind ? wup : wgate) + (size_t)e * H * F;
        Cbuf = kind ? g_bufD : g_bufC;
        obase = g_base[e]; gathered = true;
    }
    int n0 = blockIdx.x * 128;
    __shared__ unsigned As[2][KT * SMS];
    __shared__ unsigned Bs[2][KT * SMS];
    __shared__ int srcrow[128];
    int tid = threadIdx.x;
    if (tid < 128) {
        int mm = m0 + tid;
        srcrow[tid] = gathered ? ((mm < cnt) ? g_perm[obase + mm] : -1) : mm;
    }
    __syncthreads();
    int warp = tid >> 5, lane = tid & 31;
    int g = lane >> 2, tg = lane & 3;
    int wm = (warp >> 2) * 64, wn = (warp & 3) * 32;
    int arow = tid >> 1, acol = (tid & 1) * 8;
    int bk = tid >> 4, bn = (tid & 15) * 8;
    int tok = srcrow[arow];
    float gsc = gathered ? ((tok >= 0) ? g_gate[tok] : 0.f) : 1.f;
    const float* Ap = g_h2 + (size_t)((tok >= 0) ? tok : 0) * H + acol;
    const float* Bp = B + (size_t)bk * F + n0 + bn;
    float acc[4][4][4] = {};

    float4 av0 = *(const float4*)Ap, av1 = *(const float4*)(Ap + 4);
    float4 bv0 = *(const float4*)Bp, bv1 = *(const float4*)(Bp + 4);
    FILL_A(As[0], av0, av1, gsc);
    FILL_B(Bs[0], bv0, bv1);
    __syncthreads();
    int nt = H / KT;
    int buf = 0;
    for (int kt = 0; kt < nt; kt++) {
        if (kt + 1 < nt) {
            av0 = *(const float4*)(Ap + (kt + 1) * KT);
            av1 = *(const float4*)(Ap + (kt + 1) * KT + 4);
            bv0 = *(const float4*)(Bp + (size_t)(kt + 1) * KT * F);
            bv1 = *(const float4*)(Bp + (size_t)(kt + 1) * KT * F + 4);
        }
        const unsigned* Asb = As[buf];
        const unsigned* Bsb = Bs[buf];
        MMA_TILE_COMPUTE(Asb, Bsb)
        if (kt + 1 < nt) {
            FILL_A(As[buf ^ 1], av0, av1, gsc);
            FILL_B(Bs[buf ^ 1], bv0, bv1);
        }
        __syncthreads();
        buf ^= 1;
    }
#pragma unroll
    for (int mt = 0; mt < 4; mt++) {
#pragma unroll
        for (int nt2 = 0; nt2 < 4; nt2++) {
            int mi0 = wm + mt * 16 + g;
            int c = n0 + wn + nt2 * 8 + 2 * tg;
            if (m0 + mi0 < cnt)
                *(float2*)(Cbuf + (size_t)(obase + m0 + mi0) * F + c) =
                    make_float2(acc[mt][nt2][0], acc[mt][nt2][1]);
            if (m0 + mi0 + 8 < cnt)
                *(float2*)(Cbuf + (size_t)(obase + m0 + mi0 + 8) * F + c) =
                    make_float2(acc[mt][nt2][2], acc[mt][nt2][3]);
        }
    }
}

// ------------- MoE down-projections mega-GEMM (z = 0..8, silu fused, R11) ---
__global__ __launch_bounds__(256, 2)
void moe_down_tf32(const float* __restrict__ shd, const float* __restrict__ wdown,
                   float* __restrict__ out) {
    int z = blockIdx.z;
    int m0 = blockIdx.y * 128;
    int cnt, abase;
    const float* B;
    const float* Agate;
    const float* Aup;
    float* Dst;
    if (z == 0) {
        cnt = T; abase = 0;
        B = shd; Agate = g_bufA; Aup = g_bufB; Dst = out;
    } else {
        int e = z - 1;
        cnt = g_count[e];
        if (m0 >= cnt) return;
        abase = g_base[e];
        B = wdown + (size_t)e * F * H;
        Agate = g_bufC; Aup = g_bufD; Dst = g_routed;
    }
    int n0 = blockIdx.x * 128;
    __shared__ unsigned As[2][KT * SMS];
    __shared__ unsigned Bs[2][KT * SMS];
    __shared__ int rtok[128];
    int tid = threadIdx.x;
    if (tid < 128) {
        int mm = m0 + tid;
        rtok[tid] = (z == 0) ? mm : ((mm < cnt) ? g_perm[abase + mm] : -1);
    }
    __syncthreads();
    int warp = tid >> 5, lane = tid & 31;
    int g = lane >> 2, tg = lane & 3;
    int wm = (warp >> 2) * 64, wn = (warp & 3) * 32;
    int arow = tid >> 1, acol = (tid & 1) * 8;
    int bk = tid >> 4, bn = (tid & 15) * 8;
    bool arow_ok = (m0 + arow) < cnt;
    float amask = arow_ok ? 1.f : 0.f;
    size_t aoff = (size_t)(abase + (arow_ok ? (m0 + arow) : 0)) * F + acol;
    const float* Apg = Agate + aoff;
    const float* Apu = Aup + aoff;
    const float* Bp = B + (size_t)bk * H + n0 + bn;
    float acc[4][4][4] = {};

    float4 gv0 = *(const float4*)Apg, gv1 = *(const float4*)(Apg + 4);
    float4 uv0 = *(const float4*)Apu, uv1 = *(const float4*)(Apu + 4);
    float4 bv0 = *(const float4*)Bp, bv1 = *(const float4*)(Bp + 4);
    FILL_A_SILU(As[0], gv0, gv1, uv0, uv1, amask);
    FILL_B(Bs[0], bv0, bv1);
    __syncthreads();
    int nt = F / KT;
    int buf = 0;
    for (int kt = 0; kt < nt; kt++) {
        if (kt + 1 < nt) {
            gv0 = *(const float4*)(Apg + (kt + 1) * KT);
            gv1 = *(const float4*)(Apg + (kt + 1) * KT + 4);
            uv0 = *(const float4*)(Apu + (kt + 1) * KT);
            uv1 = *(const float4*)(Apu + (kt + 1) * KT + 4);
            bv0 = *(const float4*)(Bp + (size_t)(kt + 1) * KT * H);
            bv1 = *(const float4*)(Bp + (size_t)(kt + 1) * KT * H + 4);
        }
        const unsigned* Asb = As[buf];
        const unsigned* Bsb = Bs[buf];
        MMA_TILE_COMPUTE(Asb, Bsb)
        if (kt + 1 < nt) {
            FILL_A_SILU(As[buf ^ 1], gv0, gv1, uv0, uv1, amask);
            FILL_B(Bs[buf ^ 1], bv0, bv1);
        }
        __syncthreads();
        buf ^= 1;
    }
#pragma unroll
    for (int mt = 0; mt < 4; mt++) {
#pragma unroll
        for (int nt2 = 0; nt2 < 4; nt2++) {
            int mi0 = wm + mt * 16 + g;
            int c = n0 + wn + nt2 * 8 + 2 * tg;
            if (m0 + mi0 < cnt) {
                int t = rtok[mi0];
                *(float2*)(Dst + (size_t)t * H + c) =
                    make_float2(acc[mt][nt2][0], acc[mt][nt2][1]);
            }
            if (m0 + mi0 + 8 < cnt) {
                int t = rtok[mi0 + 8];
                *(float2*)(Dst + (size_t)t * H + c) =
                    make_float2(acc[mt][nt2][2], acc[mt][nt2][3]);
            }
        }
    }
}

// ---------------- rope + rms + COALESCED transpose (R11) ---------------------
__global__ void rope_rms_kernel() {
    int t0 = blockIdx.x * 32;
    int h = blockIdx.y;
    int tid = threadIdx.x;
    if (h >= NH + NKV) {
        int kh = h - NH - NKV;
        const float* src = g_qkv + NH * D + NKV * D + kh * D;
#pragma unroll
        for (int i = 0; i < 8; i++) {
            int e = tid + i * 256;
            int tl = e >> 6, d = e & 63;
            float v = src[(size_t)(t0 + tl) * QKV_N + d];
            g_vT[((size_t)kh * T + t0 + tl) * D + d] = f2tf(v);
        }
        return;
    }
    const float* src;
    unsigned* dstT;
    if (h < NH) {
        src = g_qkv + h * D;
        dstT = g_qT + (size_t)h * D * T;
    } else {
        src = g_qkv + NH * D + (h - NH) * D;
        dstT = g_kT + (size_t)(h - NH) * D * T;
    }
    __shared__ float rows[32][65];
    __shared__ float psum[32][8];
#pragma unroll
    for (int i = 0; i < 8; i++) {
        int e = tid + i * 256;
        int tl = e >> 6, d = e & 63;
        rows[tl][d] = src[(size_t)(t0 + tl) * QKV_N + d];
    }
    __syncthreads();
    int tl = tid >> 3;
    int dbase = (tid & 7) * 8;
    float vals[8];
    float sq = 0.f;
#pragma unroll
    for (int j = 0; j < 8; j++) {
        int d = dbase + j;
        int i = d & 31;
        float2 cspair = g_cs[(t0 + tl) * 32 + i];
        float x1 = rows[tl][i], x2 = rows[tl][i + 32];
        float val = (d < 32) ? (x1 * cspair.x - x2 * cspair.y)
                             : (x2 * cspair.x + x1 * cspair.y);
        vals[j] = val;
        sq += val * val;
    }
    psum[tl][tid & 7] = sq;
    __syncthreads();
    float tot = 0.f;
#pragma unroll
    for (int k = 0; k < 8; k++) tot += psum[tl][k];
    float r = rsqrtf(tot / (float)D + EPS);
#pragma unroll
    for (int j = 0; j < 8; j++) rows[tl][dbase + j] = vals[j] * r;
    __syncthreads();
#pragma unroll
    for (int i = 0; i < 8; i++) {
        int e = tid + i * 256;
        int d = e >> 5, tcol = e & 31;
        dstT[(size_t)d * T + t0 + tcol] = f2tf(rows[tcol][d]);
    }
}

// ===== tensor-core flash attention: BM=128, 256 thr, cp.async pipelined ======
#define AS 72
#define PSS 136
__global__ __launch_bounds__(256)
void attn_tc() {
    extern __shared__ unsigned usmem[];
    unsigned* Ks0 = usmem;                    // 64*AS
    unsigned* Ks1 = usmem + 64 * AS;
    unsigned* Vs0 = usmem + 2 * 64 * AS;
    unsigned* Vs1 = usmem + 3 * 64 * AS;
    unsigned* Ps  = usmem + 4 * 64 * AS;      // 64 * PSS (also Q staging)
    int qt = (int)gridDim.x - 1 - (int)blockIdx.x;  // longest first
    int head = blockIdx.y;
    int kvh = head >> 2;
    int tid = threadIdx.x, warp = tid >> 5, lane = tid & 31;
    int g = lane >> 2, tg = lane & 3;
    int q0 = qt * 128;
    int wq = warp * 16;

    const unsigned* ksrc = g_kT + (size_t)kvh * D * T;
    const unsigned* vsrc = g_vT + (size_t)kvh * T * D;

    // issue tile-0 K/V cp.async first (overlaps with Q staging below)
    for (int e4 = tid; e4 < 64 * 16; e4 += 256) {
        int d = e4 >> 4, c4 = (e4 & 15) * 4;
        cp16((unsigned)__cvta_generic_to_shared(&Ks0[d * AS + c4]),
             ksrc + (size_t)d * T + c4);
    }
    for (int e4 = tid; e4 < 64 * 16; e4 += 256) {
        int c = e4 >> 4, d4 = (e4 & 15) * 4;
        cp16((unsigned)__cvta_generic_to_shared(&Vs0[c * AS + d4]),
             vsrc + (size_t)c * D + d4);
    }
    CP_COMMIT();

    // stage Q tile [d][row 0..127] into Ps
    {
        const unsigned* qsrc = g_qT + (size_t)head * D * T + q0;
        for (int e4 = tid; e4 < 64 * 32; e4 += 256) {
            int d = e4 >> 5, r4 = (e4 & 31) * 4;
            uint4 v = *(const uint4*)(qsrc + (size_t)d * T + r4);
            *(uint4*)&Ps[d * PSS + r4] = v;
        }
    }
    __syncthreads();
    unsigned qf[8][4];
#pragma unroll
    for (int kc = 0; kc < 8; kc++) {
        qf[kc][0] = Ps[(kc * 8 + tg) * PSS + wq + g];
        qf[kc][1] = Ps[(kc * 8 + tg) * PSS + wq + g + 8];
        qf[kc][2] = Ps[(kc * 8 + tg + 4) * PSS + wq + g];
        qf[kc][3] = Ps[(kc * 8 + tg + 4) * PSS + wq + g + 8];
    }
    __syncthreads();   // everyone done reading Q from Ps before P writes

    int r0 = q0 + wq + g, r1 = r0 + 8;
    float m0 = -INFINITY, m1 = -INFINITY, l0 = 0.f, l1 = 0.f;
    float accO[8][4] = {};

    int ntiles = 2 * qt + 2;    // keys 0 .. q0+127
    int buf = 0;
    for (int j0 = 0; j0 < ntiles; j0++) {
        int k0 = j0 * 64;
        CP_WAIT0();
        __syncthreads();
        if (j0 + 1 < ntiles) {
            unsigned* Kn = buf ? Ks0 : Ks1;
            unsigned* Vn = buf ? Vs0 : Vs1;
            int kn = k0 + 64;
            for (int e4 = tid; e4 < 64 * 16; e4 += 256) {
                int d = e4 >> 4, c4 = (e4 & 15) * 4;
                cp16((unsigned)__cvta_generic_to_shared(&Kn[d * AS + c4]),
                     ksrc + (size_t)d * T + kn + c4);
            }
            for (int e4 = tid; e4 < 64 * 16; e4 += 256) {
                int c = e4 >> 4, d4 = (e4 & 15) * 4;
                cp16((unsigned)__cvta_generic_to_shared(&Vn[c * AS + d4]),
                     vsrc + (size_t)(kn + c) * D + d4);
            }
            CP_COMMIT();
        }
        const unsigned* Kb = buf ? Ks1 : Ks0;
        const unsigned* Vb = buf ? Vs1 : Vs0;
        // S = Q K^T
        float sc[8][4] = {};
#pragma unroll
        for (int kc = 0; kc < 8; kc++) {
            unsigned bfr[8][2];
#pragma unroll
            for (int n = 0; n < 8; n++) {
                bfr[n][0] = Kb[(kc * 8 + tg) * AS + n * 8 + g];
                bfr[n][1] = Kb[(kc * 8 + tg + 4) * AS + n * 8 + g];
            }
#pragma unroll
            for (int n = 0; n < 8; n++) mma_tf32(sc[n], qf[kc], bfr[n]);
        }
        // mask + online softmax
        float mx0 = -INFINITY, mx1 = -INFINITY;
#pragma unroll
        for (int n = 0; n < 8; n++) {
            int c0 = k0 + n * 8 + 2 * tg;
            float s0 = (c0 <= r0) ? sc[n][0] * ATT_SCALE : -INFINITY;
            float s1 = (c0 + 1 <= r0) ? sc[n][1] * ATT_SCALE : -INFINITY;
            float s2 = (c0 <= r1) ? sc[n][2] * ATT_SCALE : -INFINITY;
            float s3 = (c0 + 1 <= r1) ? sc[n][3] * ATT_SCALE : -INFINITY;
            sc[n][0] = s0; sc[n][1] = s1; sc[n][2] = s2; sc[n][3] = s3;
            mx0 = fmaxf(mx0, fmaxf(s0, s1));
            mx1 = fmaxf(mx1, fmaxf(s2, s3));
        }
        mx0 = fmaxf(mx0, __shfl_xor_sync(0xffffffffu, mx0, 1));
        mx0 = fmaxf(mx0, __shfl_xor_sync(0xffffffffu, mx0, 2));
        mx1 = fmaxf(mx1, __shfl_xor_sync(0xffffffffu, mx1, 1));
        mx1 = fmaxf(mx1, __shfl_xor_sync(0xffffffffu, mx1, 2));
        float nm0 = fmaxf(m0, mx0), nm1 = fmaxf(m1, mx1);
        float corr0 = __expf(m0 - nm0), corr1 = __expf(m1 - nm1);
        m0 = nm0; m1 = nm1;
        float rs0 = 0.f, rs1 = 0.f;
#pragma unroll
        for (int n = 0; n < 8; n++) {
            int cl = n * 8 + 2 * tg;
            float p0 = __expf(sc[n][0] - nm0);
            float p1 = __expf(sc[n][1] - nm0);
            float p2 = __expf(sc[n][2] - nm1);
            float p3 = __expf(sc[n][3] - nm1);
            rs0 += p0 + p1; rs1 += p2 + p3;
            Ps[cl * PSS + wq + g] = f2tf(p0);
            Ps[(cl + 1) * PSS + wq + g] = f2tf(p1);
            Ps[cl * PSS + wq + g + 8] = f2tf(p2);
            Ps[(cl + 1) * PSS + wq + g + 8] = f2tf(p3);
        }
        rs0 += __shfl_xor_sync(0xffffffffu, rs0, 1);
        rs0 += __shfl_xor_sync(0xffffffffu, rs0, 2);
        rs1 += __shfl_xor_sync(0xffffffffu, rs1, 1);
        rs1 += __shfl_xor_sync(0xffffffffu, rs1, 2);
        l0 = l0 * corr0 + rs0;
        l1 = l1 * corr1 + rs1;
#pragma unroll
        for (int n = 0; n < 8; n++) {
            accO[n][0] *= corr0; accO[n][1] *= corr0;
            accO[n][2] *= corr1; accO[n][3] *= corr1;
        }
        __syncwarp();   // Ps columns wq..wq+15 are per-warp private
        // O += P V
#pragma unroll
        for (int kc = 0; kc < 8; kc++) {
            unsigned af[4];
            af[0] = Ps[(kc * 8 + tg) * PSS + wq + g];
            af[1] = Ps[(kc * 8 + tg) * PSS + wq + g + 8];
            af[2] = Ps[(kc * 8 + tg + 4) * PSS + wq + g];
            af[3] = Ps[(kc * 8 + tg + 4) * PSS + wq + g + 8];
#pragma unroll
            for (int n = 0; n < 8; n++) {
                unsigned bfr2[2];
                bfr2[0] = Vb[(kc * 8 + tg) * AS + n * 8 + g];
                bfr2[1] = Vb[(kc * 8 + tg + 4) * AS + n * 8 + g];
                mma_tf32(accO[n], af, bfr2);
            }
        }
        buf ^= 1;
    }
    float inv0 = 1.f / l0, inv1 = 1.f / l1;
#pragma unroll
    for (int n = 0; n < 8; n++) {
        int c = head * D + n * 8 + 2 * tg;
        *(float2*)&g_ao[(size_t)r0 * (NH * D) + c] =
            make_float2(accO[n][0] * inv0, accO[n][1] * inv0);
        *(float2*)&g_ao[(size_t)r1 * (NH * D) + c] =
            make_float2(accO[n][2] * inv1, accO[n][3] * inv1);
    }
}

// ---------------- launch ------------------------------------------------------
extern "C" void kernel_launch(void* const* d_in, const int* in_sizes, int n_in,
                              void* d_out, int out_size) {
    const int* pos = (const int*)d_in[0];
    const float* hidden = (const float*)d_in[1];
    const float* ln1 = (const float*)d_in[2];
    const float* ln2 = (const float*)d_in[3];
    const float* wqkv = (const float*)d_in[4];
    const float* wo = (const float*)d_in[5];
    const float* rw = (const float*)d_in[6];
    const float* wgate = (const float*)d_in[7];
    const float* wup = (const float*)d_in[8];
    const float* wdown = (const float*)d_in[9];
    const float* shg = (const float*)d_in[10];
    const float* shu = (const float*)d_in[11];
    const float* shd = (const float*)d_in[12];
    float* out = (float*)d_out;
    float* resid = out + (size_t)T * H;

    float *p_h1, *p_h2, *p_qkv, *p_ao;
    cudaGetSymbolAddress((void**)&p_h1, g_h1);
    cudaGetSymbolAddress((void**)&p_h2, g_h2);
    cudaGetSymbolAddress((void**)&p_qkv, g_qkv);
    cudaGetSymbolAddress((void**)&p_ao, g_ao);

    static int attn_smem_set = 0;
    const int ATTN_SMEM = (4 * 64 * AS + 64 * PSS) * 4;   // 108544 B
    if (!attn_smem_set) {
        cudaFuncSetAttribute(attn_tc, cudaFuncAttributeMaxDynamicSharedMemorySize, ATTN_SMEM);
        attn_smem_set = 1;
    }

    rope_table_kernel<<<256, 256>>>(pos);   // also zeroes g_count
    rmsnorm_kernel<<<T, 256>>>(hidden, ln1, p_h1);
    gemm_tf32<<<dim3(QKV_N / 128, T / 128), 256>>>(p_h1, wqkv, p_qkv, T, QKV_N, H, nullptr);
    rope_rms_kernel<<<dim3(T / 32, NH + 2 * NKV), 256>>>();
    attn_tc<<<dim3(T / 128, NH), 256, ATTN_SMEM>>>();
    gemm_tf32<<<dim3(H / 128, T / 128), 256>>>(p_ao, wo, resid, T, H, NH * D, hidden);
    rmsnorm_router_kernel<<<T, 256>>>(resid, ln2, rw, p_h2);
    scan_scatter_kernel<<<1, 256>>>();
    moe_proj_tf32<<<dim3(F / 128, T / 128, 2 + 2 * E), 256>>>(shg, shu, wgate, wup);
    moe_down_tf32<<<dim3(H / 128, T / 128, 1 + E), 256>>>(shd, wdown, out);
    add_routed_kernel<<<(T * H) / 1024, 256>>>(out);
    (void)in_sizes; (void)n_in; (void)out_size;
}

// round 14
// speedup vs baseline: 1.2146x; 1.0190x over previous
#include <cuda_runtime.h>
#include <math.h>

#define T 2048
#define H 1024
#define NH 16
#define NKV 4
#define D 64
#define E 8
#define F 1024
#define QKV_N ((NH + 2*NKV) * D)   // 1536
#define EPS 1e-5f
#define ATT_SCALE 0.125f

// ---------------- scratch ---------------------------------------------------
__device__ float    g_h1[T * H];
__device__ float    g_qkv[T * QKV_N];
__device__ unsigned g_qT[NH * D * T];    // tf32 bits, [head][d][t]
__device__ unsigned g_kT[NKV * D * T];   // tf32 bits, [kvh][d][t]
__device__ unsigned g_vT[NKV * T * D];   // tf32 bits, [kvh][t][d]
__device__ float    g_ao[T * NH * D];
__device__ float    g_h2[T * H];
__device__ float    g_bufA[T * F];
__device__ float    g_bufB[T * F];
__device__ float    g_bufC[T * F];
__device__ float    g_bufD[T * F];
__device__ float    g_routed[T * H];
__device__ float2   g_cs[T * 32];
__device__ int      g_eidx[T];
__device__ float    g_gate[T];
__device__ int      g_perm[T];
__device__ int      g_count[E];
__device__ int      g_base[E];

// =================== TF32 tensor-core machinery ==============================
__device__ __forceinline__ unsigned f2tf(float x) {
    unsigned r;
    asm("cvt.rna.tf32.f32 %0, %1;" : "=r"(r) : "f"(x));
    return r;
}
__device__ __forceinline__ void mma_tf32(float* c, const unsigned* a, const unsigned* b) {
    asm volatile(
        "mma.sync.aligned.m16n8k8.row.col.f32.tf32.tf32.f32 "
        "{%0,%1,%2,%3},{%4,%5,%6,%7},{%8,%9},{%0,%1,%2,%3};"
        : "+f"(c[0]), "+f"(c[1]), "+f"(c[2]), "+f"(c[3])
        : "r"(a[0]), "r"(a[1]), "r"(a[2]), "r"(a[3]), "r"(b[0]), "r"(b[1]));
}
__device__ __forceinline__ void cp16(unsigned smem_addr, const void* gptr) {
    asm volatile("cp.async.ca.shared.global [%0], [%1], 16;" :: "r"(smem_addr), "l"(gptr));
}
#define CP_COMMIT() asm volatile("cp.async.commit_group;")
#define CP_WAIT0()  asm volatile("cp.async.wait_group 0;")

// ---------------- fused rmsnorm1 + rope table --------------------------------
// grid = T + 256 blocks. Blocks [0,T): rmsnorm row. Blocks [T,T+256): table.
__global__ void pre_kernel(const int* __restrict__ pos,
                           const float* __restrict__ in, const float* __restrict__ w,
                           float* __restrict__ out) {
    int tid = threadIdx.x;
    if (blockIdx.x >= T) {
        int idx = (blockIdx.x - T) * 256 + tid;   // 0..65535
        if (idx < E) g_count[idx] = 0;
        int t = idx >> 5, i = idx & 31;
        float inv = powf(500000.0f, -((float)i) / 32.0f);
        float ang = (float)pos[t] * inv;
        float sn, cs;
        sincosf(ang, &sn, &cs);
        g_cs[idx] = make_float2(cs, sn);
        return;
    }
    int row = blockIdx.x;
    const float* p = in + (size_t)row * H;
    float v[4];
    float s = 0.f;
#pragma unroll
    for (int i = 0; i < 4; i++) { v[i] = p[tid + i * 256]; s += v[i] * v[i]; }
#pragma unroll
    for (int off = 16; off; off >>= 1) s += __shfl_xor_sync(0xffffffffu, s, off);
    __shared__ float sw[8];
    if ((tid & 31) == 0) sw[tid >> 5] = s;
    __syncthreads();
    __shared__ float stot;
    if (tid == 0) {
        float t2 = 0.f;
        for (int i = 0; i < 8; i++) t2 += sw[i];
        stot = t2;
    }
    __syncthreads();
    float r = rsqrtf(stot / (float)H + EPS);
    float* o = out + (size_t)row * H;
#pragma unroll
    for (int i = 0; i < 4; i++) o[tid + i * 256] = v[i] * r * w[tid + i * 256];
}

__global__ void scan_scatter_kernel() {
    __shared__ int sbase[E];
    __shared__ int soffs[E];
    int tid = threadIdx.x;
    if (tid == 0) {
        int b = 0;
        for (int e = 0; e < E; e++) { sbase[e] = b; g_base[e] = b; b += g_count[e]; }
    }
    if (tid < E) soffs[tid] = 0;
    __syncthreads();
    for (int t = tid; t < T; t += 256) {
        int e = g_eidx[t];
        int p = sbase[e] + atomicAdd(&soffs[e], 1);
        g_perm[p] = t;
    }
}
__global__ void add_routed_kernel(float* __restrict__ out) {
    int i = blockIdx.x * blockDim.x + threadIdx.x;
    float4 a = *(const float4*)(out + i * 4);
    float4 b = *(const float4*)(g_routed + i * 4);
    a.x += b.x; a.y += b.y; a.z += b.z; a.w += b.w;
    *(float4*)(out + i * 4) = a;
}

// ---------------- rmsnorm2 + router fused -----------------------------------
__global__ void rmsnorm_router_kernel(const float* __restrict__ in,
                                      const float* __restrict__ w,
                                      const float* __restrict__ rw,
                                      float* __restrict__ out) {
    int row = blockIdx.x, tid = threadIdx.x;
    const float* p = in + (size_t)row * H;
    float v[4];
    float s = 0.f;
#pragma unroll
    for (int i = 0; i < 4; i++) { v[i] = p[tid + i * 256]; s += v[i] * v[i]; }
#pragma unroll
    for (int off = 16; off; off >>= 1) s += __shfl_xor_sync(0xffffffffu, s, off);
    __shared__ float sw[8];
    if ((tid & 31) == 0) sw[tid >> 5] = s;
    __syncthreads();
    __shared__ float stot;
    if (tid == 0) {
        float t2 = 0.f;
        for (int i = 0; i < 8; i++) t2 += sw[i];
        stot = t2;
    }
    __syncthreads();
    float r = rsqrtf(stot / (float)H + EPS);
    float* o = out + (size_t)row * H;
    float acc[E] = {};
#pragma unroll
    for (int i = 0; i < 4; i++) {
        int h = tid + i * 256;
        float hv = v[i] * r * w[h];
        o[h] = hv;
        const float* rr = rw + (size_t)h * E;
#pragma unroll
        for (int e = 0; e < E; e++) acc[e] += hv * rr[e];
    }
#pragma unroll
    for (int e = 0; e < E; e++)
#pragma unroll
        for (int off = 16; off; off >>= 1)
            acc[e] += __shfl_xor_sync(0xffffffffu, acc[e], off);
    __shared__ float sred[8][E];
    int wp = tid >> 5, lane = tid & 31;
    if (lane == 0)
        for (int e = 0; e < E; e++) sred[wp][e] = acc[e];
    __syncthreads();
    if (tid == 0) {
        float best = -INFINITY;
        int bi = 0;
        for (int e = 0; e < E; e++) {
            float vv = 0.f;
            for (int ww = 0; ww < 8; ww++) vv += sred[ww][e];
            if (vv > best) { best = vv; bi = e; }
        }
        g_eidx[row] = bi;
        g_gate[row] = 1.f / (1.f + expf(-best));
        atomicAdd(&g_count[bi], 1);
    }
}

#define KT 16
#define SMS 136

#define MMA_TILE_COMPUTE(Asb, Bsb)                                             \
    _Pragma("unroll")                                                          \
    for (int k8 = 0; k8 < KT; k8 += 8) {                                       \
        unsigned af[4][4], bf[4][2];                                           \
        _Pragma("unroll")                                                      \
        for (int mt = 0; mt < 4; mt++) {                                       \
            int mb = wm + mt * 16;                                             \
            af[mt][0] = Asb[(k8 + tg) * SMS + mb + g];                         \
            af[mt][1] = Asb[(k8 + tg) * SMS + mb + g + 8];                     \
            af[mt][2] = Asb[(k8 + tg + 4) * SMS + mb + g];                     \
            af[mt][3] = Asb[(k8 + tg + 4) * SMS + mb + g + 8];                 \
        }                                                                      \
        _Pragma("unroll")                                                      \
        for (int nt2 = 0; nt2 < 4; nt2++) {                                    \
            int nb = wn + nt2 * 8;                                             \
            bf[nt2][0] = Bsb[(k8 + tg) * SMS + nb + g];                        \
            bf[nt2][1] = Bsb[(k8 + tg + 4) * SMS + nb + g];                    \
        }                                                                      \
        _Pragma("unroll")                                                      \
        for (int mt = 0; mt < 4; mt++)                                         \
            _Pragma("unroll")                                                  \
            for (int nt2 = 0; nt2 < 4; nt2++)                                  \
                mma_tf32(acc[mt][nt2], af[mt], bf[nt2]);                       \
    }

#define FILL_A(dst, v0, v1, scale)                                             \
    do {                                                                       \
        (dst)[(acol + 0) * SMS + arow] = f2tf((v0).x * (scale));               \
        (dst)[(acol + 1) * SMS + arow] = f2tf((v0).y * (scale));               \
        (dst)[(acol + 2) * SMS + arow] = f2tf((v0).z * (scale));               \
        (dst)[(acol + 3) * SMS + arow] = f2tf((v0).w * (scale));               \
        (dst)[(acol + 4) * SMS + arow] = f2tf((v1).x * (scale));               \
        (dst)[(acol + 5) * SMS + arow] = f2tf((v1).y * (scale));               \
        (dst)[(acol + 6) * SMS + arow] = f2tf((v1).z * (scale));               \
        (dst)[(acol + 7) * SMS + arow] = f2tf((v1).w * (scale));               \
    } while (0)

#define SILU1(x) ((x) / (1.f + __expf(-(x))))
#define FILL_A_SILU(dst, gv0, gv1, uv0, uv1, mask)                             \
    do {                                                                       \
        (dst)[(acol + 0) * SMS + arow] = f2tf(SILU1((gv0).x) * (uv0).x * (mask)); \
        (dst)[(acol + 1) * SMS + arow] = f2tf(SILU1((gv0).y) * (uv0).y * (mask)); \
        (dst)[(acol + 2) * SMS + arow] = f2tf(SILU1((gv0).z) * (uv0).z * (mask)); \
        (dst)[(acol + 3) * SMS + arow] = f2tf(SILU1((gv0).w) * (uv0).w * (mask)); \
        (dst)[(acol + 4) * SMS + arow] = f2tf(SILU1((gv1).x) * (uv1).x * (mask)); \
        (dst)[(acol + 5) * SMS + arow] = f2tf(SILU1((gv1).y) * (uv1).y * (mask)); \
        (dst)[(acol + 6) * SMS + arow] = f2tf(SILU1((gv1).z) * (uv1).z * (mask)); \
        (dst)[(acol + 7) * SMS + arow] = f2tf(SILU1((gv1).w) * (uv1).w * (mask)); \
    } while (0)

#define FILL_B(dst, v0, v1)                                                    \
    do {                                                                       \
        unsigned* bd_ = (dst) + bk * SMS + bn;                                 \
        bd_[0] = f2tf((v0).x); bd_[1] = f2tf((v0).y);                          \
        bd_[2] = f2tf((v0).z); bd_[3] = f2tf((v0).w);                          \
        bd_[4] = f2tf((v1).x); bd_[5] = f2tf((v1).y);                          \
        bd_[6] = f2tf((v1).z); bd_[7] = f2tf((v1).w);                          \
    } while (0)

// ---------------- dense tf32 GEMM (R11 config; optional V-export) -----------
// qkv_mode: for output cols >= (NH+NKV)*D also store tf32 bits to g_vT.
__global__ __launch_bounds__(256)
void gemm_tf32(const float* __restrict__ A, const float* __restrict__ B,
               float* __restrict__ C, int M, int N, int K,
               const float* __restrict__ addsrc, int qkv_mode) {
    __shared__ unsigned As[2][KT * SMS];
    __shared__ unsigned Bs[2][KT * SMS];
    int tid = threadIdx.x;
    int warp = tid >> 5, lane = tid & 31;
    int g = lane >> 2, tg = lane & 3;
    int wm = (warp >> 2) * 64, wn = (warp & 3) * 32;
    int m0 = blockIdx.y * 128, n0 = blockIdx.x * 128;
    int arow = tid >> 1, acol = (tid & 1) * 8;
    int bk = tid >> 4, bn = (tid & 15) * 8;
    const float* Ap = A + (size_t)(m0 + arow) * K + acol;
    const float* Bp = B + (size_t)bk * N + n0 + bn;
    float acc[4][4][4] = {};

    float4 av0 = *(const float4*)Ap, av1 = *(const float4*)(Ap + 4);
    float4 bv0 = *(const float4*)Bp, bv1 = *(const float4*)(Bp + 4);
    FILL_A(As[0], av0, av1, 1.f);
    FILL_B(Bs[0], bv0, bv1);
    __syncthreads();
    int nt = K / KT;
    int buf = 0;
    for (int kt = 0; kt < nt; kt++) {
        if (kt + 1 < nt) {
            av0 = *(const float4*)(Ap + (kt + 1) * KT);
            av1 = *(const float4*)(Ap + (kt + 1) * KT + 4);
            bv0 = *(const float4*)(Bp + (size_t)(kt + 1) * KT * N);
            bv1 = *(const float4*)(Bp + (size_t)(kt + 1) * KT * N + 4);
        }
        const unsigned* Asb = As[buf];
        const unsigned* Bsb = Bs[buf];
        MMA_TILE_COMPUTE(Asb, Bsb)
        if (kt + 1 < nt) {
            FILL_A(As[buf ^ 1], av0, av1, 1.f);
            FILL_B(Bs[buf ^ 1], bv0, bv1);
        }
        __syncthreads();
        buf ^= 1;
    }
#pragma unroll
    for (int mt = 0; mt < 4; mt++) {
#pragma unroll
        for (int nt2 = 0; nt2 < 4; nt2++) {
            int r0 = m0 + wm + mt * 16 + g;
            int c = n0 + wn + nt2 * 8 + 2 * tg;
            float2 v0 = make_float2(acc[mt][nt2][0], acc[mt][nt2][1]);
            float2 v1 = make_float2(acc[mt][nt2][2], acc[mt][nt2][3]);
            if (addsrc) {
                float2 r = *(const float2*)(addsrc + (size_t)r0 * N + c);
                v0.x += r.x; v0.y += r.y;
                float2 r2 = *(const float2*)(addsrc + (size_t)(r0 + 8) * N + c);
                v1.x += r2.x; v1.y += r2.y;
            }
            *(float2*)(C + (size_t)r0 * N + c) = v0;
            *(float2*)(C + (size_t)(r0 + 8) * N + c) = v1;
            if (qkv_mode && c >= (NH + NKV) * D) {
                int kvh = (c - (NH + NKV) * D) >> 6;
                int d = (c - (NH + NKV) * D) & 63;
                unsigned* vp0 = g_vT + ((size_t)kvh * T + r0) * D + d;
                vp0[0] = f2tf(v0.x); vp0[1] = f2tf(v0.y);
                unsigned* vp1 = g_vT + ((size_t)kvh * T + r0 + 8) * D + d;
                vp1[0] = f2tf(v1.x); vp1[1] = f2tf(v1.y);
            }
        }
    }
}

// ------------- MoE up-projections mega-GEMM (z = 0..17) ---------------------
__global__ __launch_bounds__(256)
void moe_proj_tf32(const float* __restrict__ shg, const float* __restrict__ shu,
                   const float* __restrict__ wgate, const float* __restrict__ wup) {
    int z = blockIdx.z;
    int m0 = blockIdx.y * 128;
    int cnt, obase;
    const float* B;
    float* Cbuf;
    bool gathered;
    if (z < 2) {
        B = z ? shu : shg;
        Cbuf = z ? g_bufB : g_bufA;
        cnt = T; obase = 0; gathered = false;
    } else {
        int e = (z - 2) >> 1, kind = (z - 2) & 1;
        cnt = g_count[e];
        if (m0 >= cnt) return;
        B = (kind ? wup : wgate) + (size_t)e * H * F;
        Cbuf = kind ? g_bufD : g_bufC;
        obase = g_base[e]; gathered = true;
    }
    int n0 = blockIdx.x * 128;
    __shared__ unsigned As[2][KT * SMS];
    __shared__ unsigned Bs[2][KT * SMS];
    __shared__ int srcrow[128];
    int tid = threadIdx.x;
    if (tid < 128) {
        int mm = m0 + tid;
        srcrow[tid] = gathered ? ((mm < cnt) ? g_perm[obase + mm] : -1) : mm;
    }
    __syncthreads();
    int warp = tid >> 5, lane = tid & 31;
    int g = lane >> 2, tg = lane & 3;
    int wm = (warp >> 2) * 64, wn = (warp & 3) * 32;
    int arow = tid >> 1, acol = (tid & 1) * 8;
    int bk = tid >> 4, bn = (tid & 15) * 8;
    int tok = srcrow[arow];
    float gsc = gathered ? ((tok >= 0) ? g_gate[tok] : 0.f) : 1.f;
    const float* Ap = g_h2 + (size_t)((tok >= 0) ? tok : 0) * H + acol;
    const float* Bp = B + (size_t)bk * F + n0 + bn;
    float acc[4][4][4] = {};

    float4 av0 = *(const float4*)Ap, av1 = *(const float4*)(Ap + 4);
    float4 bv0 = *(const float4*)Bp, bv1 = *(const float4*)(Bp + 4);
    FILL_A(As[0], av0, av1, gsc);
    FILL_B(Bs[0], bv0, bv1);
    __syncthreads();
    int nt = H / KT;
    int buf = 0;
    for (int kt = 0; kt < nt; kt++) {
        if (kt + 1 < nt) {
            av0 = *(const float4*)(Ap + (kt + 1) * KT);
            av1 = *(const float4*)(Ap + (kt + 1) * KT + 4);
            bv0 = *(const float4*)(Bp + (size_t)(kt + 1) * KT * F);
            bv1 = *(const float4*)(Bp + (size_t)(kt + 1) * KT * F + 4);
        }
        const unsigned* Asb = As[buf];
        const unsigned* Bsb = Bs[buf];
        MMA_TILE_COMPUTE(Asb, Bsb)
        if (kt + 1 < nt) {
            FILL_A(As[buf ^ 1], av0, av1, gsc);
            FILL_B(Bs[buf ^ 1], bv0, bv1);
        }
        __syncthreads();
        buf ^= 1;
    }
#pragma unroll
    for (int mt = 0; mt < 4; mt++) {
#pragma unroll
        for (int nt2 = 0; nt2 < 4; nt2++) {
            int mi0 = wm + mt * 16 + g;
            int c = n0 + wn + nt2 * 8 + 2 * tg;
            if (m0 + mi0 < cnt)
                *(float2*)(Cbuf + (size_t)(obase + m0 + mi0) * F + c) =
                    make_float2(acc[mt][nt2][0], acc[mt][nt2][1]);
            if (m0 + mi0 + 8 < cnt)
                *(float2*)(Cbuf + (size_t)(obase + m0 + mi0 + 8) * F + c) =
                    make_float2(acc[mt][nt2][2], acc[mt][nt2][3]);
        }
    }
}

// ------------- MoE down-projections mega-GEMM (z = 0..8, silu fused) --------
__global__ __launch_bounds__(256, 2)
void moe_down_tf32(const float* __restrict__ shd, const float* __restrict__ wdown,
                   float* __restrict__ out) {
    int z = blockIdx.z;
    int m0 = blockIdx.y * 128;
    int cnt, abase;
    const float* B;
    const float* Agate;
    const float* Aup;
    float* Dst;
    if (z == 0) {
        cnt = T; abase = 0;
        B = shd; Agate = g_bufA; Aup = g_bufB; Dst = out;
    } else {
        int e = z - 1;
        cnt = g_count[e];
        if (m0 >= cnt) return;
        abase = g_base[e];
        B = wdown + (size_t)e * F * H;
        Agate = g_bufC; Aup = g_bufD; Dst = g_routed;
    }
    int n0 = blockIdx.x * 128;
    __shared__ unsigned As[2][KT * SMS];
    __shared__ unsigned Bs[2][KT * SMS];
    __shared__ int rtok[128];
    int tid = threadIdx.x;
    if (tid < 128) {
        int mm = m0 + tid;
        rtok[tid] = (z == 0) ? mm : ((mm < cnt) ? g_perm[abase + mm] : -1);
    }
    __syncthreads();
    int warp = tid >> 5, lane = tid & 31;
    int g = lane >> 2, tg = lane & 3;
    int wm = (warp >> 2) * 64, wn = (warp & 3) * 32;
    int arow = tid >> 1, acol = (tid & 1) * 8;
    int bk = tid >> 4, bn = (tid & 15) * 8;
    bool arow_ok = (m0 + arow) < cnt;
    float amask = arow_ok ? 1.f : 0.f;
    size_t aoff = (size_t)(abase + (arow_ok ? (m0 + arow) : 0)) * F + acol;
    const float* Apg = Agate + aoff;
    const float* Apu = Aup + aoff;
    const float* Bp = B + (size_t)bk * H + n0 + bn;
    float acc[4][4][4] = {};

    float4 gv0 = *(const float4*)Apg, gv1 = *(const float4*)(Apg + 4);
    float4 uv0 = *(const float4*)Apu, uv1 = *(const float4*)(Apu + 4);
    float4 bv0 = *(const float4*)Bp, bv1 = *(const float4*)(Bp + 4);
    FILL_A_SILU(As[0], gv0, gv1, uv0, uv1, amask);
    FILL_B(Bs[0], bv0, bv1);
    __syncthreads();
    int nt = F / KT;
    int buf = 0;
    for (int kt = 0; kt < nt; kt++) {
        if (kt + 1 < nt) {
            gv0 = *(const float4*)(Apg + (kt + 1) * KT);
            gv1 = *(const float4*)(Apg + (kt + 1) * KT + 4);
            uv0 = *(const float4*)(Apu + (kt + 1) * KT);
            uv1 = *(const float4*)(Apu + (kt + 1) * KT + 4);
            bv0 = *(const float4*)(Bp + (size_t)(kt + 1) * KT * H);
            bv1 = *(const float4*)(Bp + (size_t)(kt + 1) * KT * H + 4);
        }
        const unsigned* Asb = As[buf];
        const unsigned* Bsb = Bs[buf];
        MMA_TILE_COMPUTE(Asb, Bsb)
        if (kt + 1 < nt) {
            FILL_A_SILU(As[buf ^ 1], gv0, gv1, uv0, uv1, amask);
            FILL_B(Bs[buf ^ 1], bv0, bv1);
        }
        __syncthreads();
        buf ^= 1;
    }
#pragma unroll
    for (int mt = 0; mt < 4; mt++) {
#pragma unroll
        for (int nt2 = 0; nt2 < 4; nt2++) {
            int mi0 = wm + mt * 16 + g;
            int c = n0 + wn + nt2 * 8 + 2 * tg;
            if (m0 + mi0 < cnt) {
                int t = rtok[mi0];
                *(float2*)(Dst + (size_t)t * H + c) =
                    make_float2(acc[mt][nt2][0], acc[mt][nt2][1]);
            }
            if (m0 + mi0 + 8 < cnt) {
                int t = rtok[mi0 + 8];
                *(float2*)(Dst + (size_t)t * H + c) =
                    make_float2(acc[mt][nt2][2], acc[mt][nt2][3]);
            }
        }
    }
}

// ---------------- rope + rms + COALESCED transpose (q,k only) ----------------
// grid (T/32, 20): head y (q:0..15, k:16..19), 32 tokens/block
__global__ void rope_rms_kernel() {
    int t0 = blockIdx.x * 32;
    int h = blockIdx.y;
    int tid = threadIdx.x;
    const float* src;
    unsigned* dstT;
    if (h < NH) {
        src = g_qkv + h * D;
        dstT = g_qT + (size_t)h * D * T;
    } else {
        src = g_qkv + NH * D + (h - NH) * D;
        dstT = g_kT + (size_t)(h - NH) * D * T;
    }
    __shared__ float rows[32][65];
    __shared__ float psum[32][8];
#pragma unroll
    for (int i = 0; i < 8; i++) {
        int e = tid + i * 256;
        int tl = e >> 6, d = e & 63;
        rows[tl][d] = src[(size_t)(t0 + tl) * QKV_N + d];
    }
    __syncthreads();
    int tl = tid >> 3;
    int dbase = (tid & 7) * 8;
    float vals[8];
    float sq = 0.f;
#pragma unroll
    for (int j = 0; j < 8; j++) {
        int d = dbase + j;
        int i = d & 31;
        float2 cspair = g_cs[(t0 + tl) * 32 + i];
        float x1 = rows[tl][i], x2 = rows[tl][i + 32];
        float val = (d < 32) ? (x1 * cspair.x - x2 * cspair.y)
                             : (x2 * cspair.x + x1 * cspair.y);
        vals[j] = val;
        sq += val * val;
    }
    psum[tl][tid & 7] = sq;
    __syncthreads();
    float tot = 0.f;
#pragma unroll
    for (int k = 0; k < 8; k++) tot += psum[tl][k];
    float r = rsqrtf(tot / (float)D + EPS);
#pragma unroll
    for (int j = 0; j < 8; j++) rows[tl][dbase + j] = vals[j] * r;
    __syncthreads();
#pragma unroll
    for (int i = 0; i < 8; i++) {
        int e = tid + i * 256;
        int d = e >> 5, tcol = e & 31;
        dstT[(size_t)d * T + t0 + tcol] = f2tf(rows[tcol][d]);
    }
}

// ========== tensor-core flash attention (R11: BM=64, cp.async) ===============
#define AS 72
__global__ __launch_bounds__(128)
void attn_tc() {
    extern __shared__ unsigned usmem[];
    unsigned* Ks0 = usmem;
    unsigned* Ks1 = usmem + 64 * AS;
    unsigned* Vs0 = usmem + 2 * 64 * AS;
    unsigned* Vs1 = usmem + 3 * 64 * AS;
    unsigned* Ps  = usmem + 4 * 64 * AS;
    int qt = (int)gridDim.x - 1 - (int)blockIdx.x;
    int head = blockIdx.y;
    int kvh = head >> 2;
    int tid = threadIdx.x, warp = tid >> 5, lane = tid & 31;
    int g = lane >> 2, tg = lane & 3;
    int q0 = qt * 64;
    int wq = warp * 16;

    const unsigned* ksrc = g_kT + (size_t)kvh * D * T;
    const unsigned* vsrc = g_vT + (size_t)kvh * T * D;

    {
        const unsigned* qsrc = g_qT + (size_t)head * D * T + q0;
        for (int e4 = tid; e4 < 64 * 16; e4 += 128) {
            int d = e4 >> 4, r4 = (e4 & 15) * 4;
            uint4 v = *(const uint4*)(qsrc + (size_t)d * T + r4);
            *(uint4*)&Ks0[d * AS + r4] = v;
        }
    }
    __syncthreads();
    unsigned qf[8][4];
#pragma unroll
    for (int kc = 0; kc < 8; kc++) {
        qf[kc][0] = Ks0[(kc * 8 + tg) * AS + wq + g];
        qf[kc][1] = Ks0[(kc * 8 + tg) * AS + wq + g + 8];
        qf[kc][2] = Ks0[(kc * 8 + tg + 4) * AS + wq + g];
        qf[kc][3] = Ks0[(kc * 8 + tg + 4) * AS + wq + g + 8];
    }
    __syncthreads();

    int r0 = q0 + wq + g, r1 = r0 + 8;
    float m0 = -INFINITY, m1 = -INFINITY, l0 = 0.f, l1 = 0.f;
    float accO[8][4] = {};

    {
        for (int e4 = tid; e4 < 64 * 16; e4 += 128) {
            int d = e4 >> 4, c4 = (e4 & 15) * 4;
            cp16((unsigned)__cvta_generic_to_shared(&Ks0[d * AS + c4]),
                 ksrc + (size_t)d * T + c4);
        }
        for (int e4 = tid; e4 < 64 * 16; e4 += 128) {
            int c = e4 >> 4, d4 = (e4 & 15) * 4;
            cp16((unsigned)__cvta_generic_to_shared(&Vs0[c * AS + d4]),
                 vsrc + (size_t)c * D + d4);
        }
        CP_COMMIT();
    }

    int buf = 0;
    for (int j0 = 0; j0 <= qt; j0++) {
        int k0 = j0 * 64;
        CP_WAIT0();
        __syncthreads();
        if (j0 < qt) {
            unsigned* Kn = buf ? Ks0 : Ks1;
            unsigned* Vn = buf ? Vs0 : Vs1;
            int kn = k0 + 64;
            for (int e4 = tid; e4 < 64 * 16; e4 += 128) {
                int d = e4 >> 4, c4 = (e4 & 15) * 4;
                cp16((unsigned)__cvta_generic_to_shared(&Kn[d * AS + c4]),
                     ksrc + (size_t)d * T + kn + c4);
            }
            for (int e4 = tid; e4 < 64 * 16; e4 += 128) {
                int c = e4 >> 4, d4 = (e4 & 15) * 4;
                cp16((unsigned)__cvta_generic_to_shared(&Vn[c * AS + d4]),
                     vsrc + (size_t)(kn + c) * D + d4);
            }
            CP_COMMIT();
        }
        const unsigned* Kb = buf ? Ks1 : Ks0;
        const unsigned* Vb = buf ? Vs1 : Vs0;
        float sc[8][4] = {};
#pragma unroll
        for (int kc = 0; kc < 8; kc++) {
            unsigned bfr[8][2];
#pragma unroll
            for (int n = 0; n < 8; n++) {
                bfr[n][0] = Kb[(kc * 8 + tg) * AS + n * 8 + g];
                bfr[n][1] = Kb[(kc * 8 + tg + 4) * AS + n * 8 + g];
            }
#pragma unroll
            for (int n = 0; n < 8; n++) mma_tf32(sc[n], qf[kc], bfr[n]);
        }
        float mx0 = -INFINITY, mx1 = -INFINITY;
#pragma unroll
        for (int n = 0; n < 8; n++) {
            int c0 = k0 + n * 8 + 2 * tg;
            float s0 = (c0 <= r0) ? sc[n][0] * ATT_SCALE : -INFINITY;
            float s1 = (c0 + 1 <= r0) ? sc[n][1] * ATT_SCALE : -INFINITY;
            float s2 = (c0 <= r1) ? sc[n][2] * ATT_SCALE : -INFINITY;
            float s3 = (c0 + 1 <= r1) ? sc[n][3] * ATT_SCALE : -INFINITY;
            sc[n][0] = s0; sc[n][1] = s1; sc[n][2] = s2; sc[n][3] = s3;
            mx0 = fmaxf(mx0, fmaxf(s0, s1));
            mx1 = fmaxf(mx1, fmaxf(s2, s3));
        }
        mx0 = fmaxf(mx0, __shfl_xor_sync(0xffffffffu, mx0, 1));
        mx0 = fmaxf(mx0, __shfl_xor_sync(0xffffffffu, mx0, 2));
        mx1 = fmaxf(mx1, __shfl_xor_sync(0xffffffffu, mx1, 1));
        mx1 = fmaxf(mx1, __shfl_xor_sync(0xffffffffu, mx1, 2));
        float nm0 = fmaxf(m0, mx0), nm1 = fmaxf(m1, mx1);
        float corr0 = __expf(m0 - nm0), corr1 = __expf(m1 - nm1);
        m0 = nm0; m1 = nm1;
        float rs0 = 0.f, rs1 = 0.f;
#pragma unroll
        for (int n = 0; n < 8; n++) {
            int cl = n * 8 + 2 * tg;
            float p0 = __expf(sc[n][0] - nm0);
            float p1 = __expf(sc[n][1] - nm0);
            float p2 = __expf(sc[n][2] - nm1);
            float p3 = __expf(sc[n][3] - nm1);
            rs0 += p0 + p1; rs1 += p2 + p3;
            Ps[cl * AS + wq + g] = f2tf(p0);
            Ps[(cl + 1) * AS + wq + g] = f2tf(p1);
            Ps[cl * AS + wq + g + 8] = f2tf(p2);
            Ps[(cl + 1) * AS + wq + g + 8] = f2tf(p3);
        }
        rs0 += __shfl_xor_sync(0xffffffffu, rs0, 1);
        rs0 += __shfl_xor_sync(0xffffffffu, rs0, 2);
        rs1 += __shfl_xor_sync(0xffffffffu, rs1, 1);
        rs1 += __shfl_xor_sync(0xffffffffu, rs1, 2);
        l0 = l0 * corr0 + rs0;
        l1 = l1 * corr1 + rs1;
#pragma unroll
        for (int n = 0; n < 8; n++) {
            accO[n][0] *= corr0; accO[n][1] *= corr0;
            accO[n][2] *= corr1; accO[n][3] *= corr1;
        }
        __syncwarp();
#pragma unroll
        for (int kc = 0; kc < 8; kc++) {
            unsigned af[4];
            af[0] = Ps[(kc * 8 + tg) * AS + wq + g];
            af[1] = Ps[(kc * 8 + tg) * AS + wq + g + 8];
            af[2] = Ps[(kc * 8 + tg + 4) * AS + wq + g];
            af[3] = Ps[(kc * 8 + tg + 4) * AS + wq + g + 8];
#pragma unroll
            for (int n = 0; n < 8; n++) {
                unsigned bfr2[2];
                bfr2[0] = Vb[(kc * 8 + tg) * AS + n * 8 + g];
                bfr2[1] = Vb[(kc * 8 + tg + 4) * AS + n * 8 + g];
                mma_tf32(accO[n], af, bfr2);
            }
        }
        buf ^= 1;
    }
    float inv0 = 1.f / l0, inv1 = 1.f / l1;
#pragma unroll
    for (int n = 0; n < 8; n++) {
        int c = head * D + n * 8 + 2 * tg;
        *(float2*)&g_ao[(size_t)r0 * (NH * D) + c] =
            make_float2(accO[n][0] * inv0, accO[n][1] * inv0);
        *(float2*)&g_ao[(size_t)r1 * (NH * D) + c] =
            make_float2(accO[n][2] * inv1, accO[n][3] * inv1);
    }
}

// ---------------- launch ------------------------------------------------------
extern "C" void kernel_launch(void* const* d_in, const int* in_sizes, int n_in,
                              void* d_out, int out_size) {
    const int* pos = (const int*)d_in[0];
    const float* hidden = (const float*)d_in[1];
    const float* ln1 = (const float*)d_in[2];
    const float* ln2 = (const float*)d_in[3];
    const float* wqkv = (const float*)d_in[4];
    const float* wo = (const float*)d_in[5];
    const float* rw = (const float*)d_in[6];
    const float* wgate = (const float*)d_in[7];
    const float* wup = (const float*)d_in[8];
    const float* wdown = (const float*)d_in[9];
    const float* shg = (const float*)d_in[10];
    const float* shu = (const float*)d_in[11];
    const float* shd = (const float*)d_in[12];
    float* out = (float*)d_out;
    float* resid = out + (size_t)T * H;

    float *p_h1, *p_h2, *p_qkv, *p_ao;
    cudaGetSymbolAddress((void**)&p_h1, g_h1);
    cudaGetSymbolAddress((void**)&p_h2, g_h2);
    cudaGetSymbolAddress((void**)&p_qkv, g_qkv);
    cudaGetSymbolAddress((void**)&p_ao, g_ao);

    static int attn_smem_set = 0;
    const int ATTN_SMEM = 5 * 64 * AS * 4;   // 92160 B
    if (!attn_smem_set) {
        cudaFuncSetAttribute(attn_tc, cudaFuncAttributeMaxDynamicSharedMemorySize, ATTN_SMEM);
        attn_smem_set = 1;
    }

    // fused rmsnorm1 + rope table (+ g_count zero)
    pre_kernel<<<T + 256, 256>>>(pos, hidden, ln1, p_h1);
    gemm_tf32<<<dim3(QKV_N / 128, T / 128), 256>>>(p_h1, wqkv, p_qkv, T, QKV_N, H, nullptr, 1);
    rope_rms_kernel<<<dim3(T / 32, NH + NKV), 256>>>();
    attn_tc<<<dim3(T / 64, NH), 128, ATTN_SMEM>>>();
    gemm_tf32<<<dim3(H / 128, T / 128), 256>>>(p_ao, wo, resid, T, H, NH * D, hidden, 0);
    rmsnorm_router_kernel<<<T, 256>>>(resid, ln2, rw, p_h2);
    scan_scatter_kernel<<<1, 256>>>();
    moe_proj_tf32<<<dim3(F / 128, T / 128, 2 + 2 * E), 256>>>(shg, shu, wgate, wup);
    moe_down_tf32<<<dim3(H / 128, T / 128, 1 + E), 256>>>(shd, wdown, out);
    add_routed_kernel<<<(T * H) / 1024, 256>>>(out);
    (void)in_sizes; (void)n_in; (void)out_size;
}

// round 15
// speedup vs baseline: 1.2477x; 1.0273x over previous
#include <cuda_runtime.h>
#include <math.h>

#define T 2048
#define H 1024
#define NH 16
#define NKV 4
#define D 64
#define E 8
#define F 1024
#define QKV_N ((NH + 2*NKV) * D)   // 1536
#define EPS 1e-5f
#define ATT_SCALE 0.125f

// ---------------- scratch ---------------------------------------------------
__device__ float    g_h1[T * H];
__device__ float    g_qkv[T * QKV_N];
__device__ unsigned g_qT[NH * D * T];    // tf32 bits, [head][d][t]
__device__ unsigned g_kT[NKV * D * T];   // tf32 bits, [kvh][d][t]
__device__ unsigned g_vT[NKV * T * D];   // tf32 bits, [kvh][t][d]
__device__ float    g_ao[T * NH * D];
__device__ float    g_h2[T * H];
__device__ float    g_bufA[T * F];
__device__ float    g_bufB[T * F];
__device__ float    g_bufC[T * F];
__device__ float    g_bufD[T * F];
__device__ float    g_routed[T * H];
__device__ float2   g_cs[T * 32];
__device__ int      g_eidx[T];
__device__ float    g_gate[T];
__device__ int      g_perm[T];
__device__ int      g_count[E];
__device__ int      g_base[E];

// =================== TF32 tensor-core machinery ==============================
__device__ __forceinline__ unsigned f2tf(float x) {
    unsigned r;
    asm("cvt.rna.tf32.f32 %0, %1;" : "=r"(r) : "f"(x));
    return r;
}
__device__ __forceinline__ void mma_tf32(float* c, const unsigned* a, const unsigned* b) {
    asm volatile(
        "mma.sync.aligned.m16n8k8.row.col.f32.tf32.tf32.f32 "
        "{%0,%1,%2,%3},{%4,%5,%6,%7},{%8,%9},{%0,%1,%2,%3};"
        : "+f"(c[0]), "+f"(c[1]), "+f"(c[2]), "+f"(c[3])
        : "r"(a[0]), "r"(a[1]), "r"(a[2]), "r"(a[3]), "r"(b[0]), "r"(b[1]));
}
__device__ __forceinline__ void cp16(unsigned smem_addr, const void* gptr) {
    asm volatile("cp.async.ca.shared.global [%0], [%1], 16;" :: "r"(smem_addr), "l"(gptr));
}
#define CP_COMMIT() asm volatile("cp.async.commit_group;")
#define CP_WAIT0()  asm volatile("cp.async.wait_group 0;")

// ---------------- fused rmsnorm1 + rope table --------------------------------
__global__ void pre_kernel(const int* __restrict__ pos,
                           const float* __restrict__ in, const float* __restrict__ w,
                           float* __restrict__ out) {
    int tid = threadIdx.x;
    if (blockIdx.x >= T) {
        int idx = (blockIdx.x - T) * 256 + tid;
        if (idx < E) g_count[idx] = 0;
        int t = idx >> 5, i = idx & 31;
        float inv = powf(500000.0f, -((float)i) / 32.0f);
        float ang = (float)pos[t] * inv;
        float sn, cs;
        sincosf(ang, &sn, &cs);
        g_cs[idx] = make_float2(cs, sn);
        return;
    }
    int row = blockIdx.x;
    const float* p = in + (size_t)row * H;
    float v[4];
    float s = 0.f;
#pragma unroll
    for (int i = 0; i < 4; i++) { v[i] = p[tid + i * 256]; s += v[i] * v[i]; }
#pragma unroll
    for (int off = 16; off; off >>= 1) s += __shfl_xor_sync(0xffffffffu, s, off);
    __shared__ float sw[8];
    if ((tid & 31) == 0) sw[tid >> 5] = s;
    __syncthreads();
    __shared__ float stot;
    if (tid == 0) {
        float t2 = 0.f;
        for (int i = 0; i < 8; i++) t2 += sw[i];
        stot = t2;
    }
    __syncthreads();
    float r = rsqrtf(stot / (float)H + EPS);
    float* o = out + (size_t)row * H;
#pragma unroll
    for (int i = 0; i < 4; i++) o[tid + i * 256] = v[i] * r * w[tid + i * 256];
}

__global__ void scan_scatter_kernel() {
    __shared__ int sbase[E];
    __shared__ int soffs[E];
    int tid = threadIdx.x;
    if (tid == 0) {
        int b = 0;
        for (int e = 0; e < E; e++) { sbase[e] = b; g_base[e] = b; b += g_count[e]; }
    }
    if (tid < E) soffs[tid] = 0;
    __syncthreads();
    for (int t = tid; t < T; t += 256) {
        int e = g_eidx[t];
        int p = sbase[e] + atomicAdd(&soffs[e], 1);
        g_perm[p] = t;
    }
}
__global__ void add_routed_kernel(float* __restrict__ out) {
    int i = blockIdx.x * blockDim.x + threadIdx.x;
    float4 a = *(const float4*)(out + i * 4);
    float4 b = *(const float4*)(g_routed + i * 4);
    a.x += b.x; a.y += b.y; a.z += b.z; a.w += b.w;
    *(float4*)(out + i * 4) = a;
}

// ---------------- rmsnorm2 + router fused -----------------------------------
__global__ void rmsnorm_router_kernel(const float* __restrict__ in,
                                      const float* __restrict__ w,
                                      const float* __restrict__ rw,
                                      float* __restrict__ out) {
    int row = blockIdx.x, tid = threadIdx.x;
    const float* p = in + (size_t)row * H;
    float v[4];
    float s = 0.f;
#pragma unroll
    for (int i = 0; i < 4; i++) { v[i] = p[tid + i * 256]; s += v[i] * v[i]; }
#pragma unroll
    for (int off = 16; off; off >>= 1) s += __shfl_xor_sync(0xffffffffu, s, off);
    __shared__ float sw[8];
    if ((tid & 31) == 0) sw[tid >> 5] = s;
    __syncthreads();
    __shared__ float stot;
    if (tid == 0) {
        float t2 = 0.f;
        for (int i = 0; i < 8; i++) t2 += sw[i];
        stot = t2;
    }
    __syncthreads();
    float r = rsqrtf(stot / (float)H + EPS);
    float* o = out + (size_t)row * H;
    float acc[E] = {};
#pragma unroll
    for (int i = 0; i < 4; i++) {
        int h = tid + i * 256;
        float hv = v[i] * r * w[h];
        o[h] = hv;
        const float* rr = rw + (size_t)h * E;
#pragma unroll
        for (int e = 0; e < E; e++) acc[e] += hv * rr[e];
    }
#pragma unroll
    for (int e = 0; e < E; e++)
#pragma unroll
        for (int off = 16; off; off >>= 1)
            acc[e] += __shfl_xor_sync(0xffffffffu, acc[e], off);
    __shared__ float sred[8][E];
    int wp = tid >> 5, lane = tid & 31;
    if (lane == 0)
        for (int e = 0; e < E; e++) sred[wp][e] = acc[e];
    __syncthreads();
    if (tid == 0) {
        float best = -INFINITY;
        int bi = 0;
        for (int e = 0; e < E; e++) {
            float vv = 0.f;
            for (int ww = 0; ww < 8; ww++) vv += sred[ww][e];
            if (vv > best) { best = vv; bi = e; }
        }
        g_eidx[row] = bi;
        g_gate[row] = 1.f / (1.f + expf(-best));
        atomicAdd(&g_count[bi], 1);
    }
}

#define KT 16
#define SMS 136

#define MMA_TILE_COMPUTE(Asb, Bsb)                                             \
    _Pragma("unroll")                                                          \
    for (int k8 = 0; k8 < KT; k8 += 8) {                                       \
        unsigned af[4][4], bf[4][2];                                           \
        _Pragma("unroll")                                                      \
        for (int mt = 0; mt < 4; mt++) {                                       \
            int mb = wm + mt * 16;                                             \
            af[mt][0] = Asb[(k8 + tg) * SMS + mb + g];                         \
            af[mt][1] = Asb[(k8 + tg) * SMS + mb + g + 8];                     \
            af[mt][2] = Asb[(k8 + tg + 4) * SMS + mb + g];                     \
            af[mt][3] = Asb[(k8 + tg + 4) * SMS + mb + g + 8];                 \
        }                                                                      \
        _Pragma("unroll")                                                      \
        for (int nt2 = 0; nt2 < 4; nt2++) {                                    \
            int nb = wn + nt2 * 8;                                             \
            bf[nt2][0] = Bsb[(k8 + tg) * SMS + nb + g];                        \
            bf[nt2][1] = Bsb[(k8 + tg + 4) * SMS + nb + g];                    \
        }                                                                      \
        _Pragma("unroll")                                                      \
        for (int mt = 0; mt < 4; mt++)                                         \
            _Pragma("unroll")                                                  \
            for (int nt2 = 0; nt2 < 4; nt2++)                                  \
                mma_tf32(acc[mt][nt2], af[mt], bf[nt2]);                       \
    }

#define FILL_A(dst, v0, v1, scale)                                             \
    do {                                                                       \
        (dst)[(acol + 0) * SMS + arow] = f2tf((v0).x * (scale));               \
        (dst)[(acol + 1) * SMS + arow] = f2tf((v0).y * (scale));               \
        (dst)[(acol + 2) * SMS + arow] = f2tf((v0).z * (scale));               \
        (dst)[(acol + 3) * SMS + arow] = f2tf((v0).w * (scale));               \
        (dst)[(acol + 4) * SMS + arow] = f2tf((v1).x * (scale));               \
        (dst)[(acol + 5) * SMS + arow] = f2tf((v1).y * (scale));               \
        (dst)[(acol + 6) * SMS + arow] = f2tf((v1).z * (scale));               \
        (dst)[(acol + 7) * SMS + arow] = f2tf((v1).w * (scale));               \
    } while (0)

#define SILU1(x) ((x) / (1.f + __expf(-(x))))
#define FILL_A_SILU(dst, gv0, gv1, uv0, uv1, mask)                             \
    do {                                                                       \
        (dst)[(acol + 0) * SMS + arow] = f2tf(SILU1((gv0).x) * (uv0).x * (mask)); \
        (dst)[(acol + 1) * SMS + arow] = f2tf(SILU1((gv0).y) * (uv0).y * (mask)); \
        (dst)[(acol + 2) * SMS + arow] = f2tf(SILU1((gv0).z) * (uv0).z * (mask)); \
        (dst)[(acol + 3) * SMS + arow] = f2tf(SILU1((gv0).w) * (uv0).w * (mask)); \
        (dst)[(acol + 4) * SMS + arow] = f2tf(SILU1((gv1).x) * (uv1).x * (mask)); \
        (dst)[(acol + 5) * SMS + arow] = f2tf(SILU1((gv1).y) * (uv1).y * (mask)); \
        (dst)[(acol + 6) * SMS + arow] = f2tf(SILU1((gv1).z) * (uv1).z * (mask)); \
        (dst)[(acol + 7) * SMS + arow] = f2tf(SILU1((gv1).w) * (uv1).w * (mask)); \
    } while (0)

#define FILL_B(dst, v0, v1)                                                    \
    do {                                                                       \
        unsigned* bd_ = (dst) + bk * SMS + bn;                                 \
        bd_[0] = f2tf((v0).x); bd_[1] = f2tf((v0).y);                          \
        bd_[2] = f2tf((v0).z); bd_[3] = f2tf((v0).w);                          \
        bd_[4] = f2tf((v1).x); bd_[5] = f2tf((v1).y);                          \
        bd_[6] = f2tf((v1).z); bd_[7] = f2tf((v1).w);                          \
    } while (0)

// ---------------- dense tf32 GEMM (optional V-export) ------------------------
__global__ __launch_bounds__(256)
void gemm_tf32(const float* __restrict__ A, const float* __restrict__ B,
               float* __restrict__ C, int M, int N, int K,
               const float* __restrict__ addsrc, int qkv_mode) {
    __shared__ unsigned As[2][KT * SMS];
    __shared__ unsigned Bs[2][KT * SMS];
    int tid = threadIdx.x;
    int warp = tid >> 5, lane = tid & 31;
    int g = lane >> 2, tg = lane & 3;
    int wm = (warp >> 2) * 64, wn = (warp & 3) * 32;
    int m0 = blockIdx.y * 128, n0 = blockIdx.x * 128;
    int arow = tid >> 1, acol = (tid & 1) * 8;
    int bk = tid >> 4, bn = (tid & 15) * 8;
    const float* Ap = A + (size_t)(m0 + arow) * K + acol;
    const float* Bp = B + (size_t)bk * N + n0 + bn;
    float acc[4][4][4] = {};

    float4 av0 = *(const float4*)Ap, av1 = *(const float4*)(Ap + 4);
    float4 bv0 = *(const float4*)Bp, bv1 = *(const float4*)(Bp + 4);
    FILL_A(As[0], av0, av1, 1.f);
    FILL_B(Bs[0], bv0, bv1);
    __syncthreads();
    int nt = K / KT;
    int buf = 0;
    for (int kt = 0; kt < nt; kt++) {
        if (kt + 1 < nt) {
            av0 = *(const float4*)(Ap + (kt + 1) * KT);
            av1 = *(const float4*)(Ap + (kt + 1) * KT + 4);
            bv0 = *(const float4*)(Bp + (size_t)(kt + 1) * KT * N);
            bv1 = *(const float4*)(Bp + (size_t)(kt + 1) * KT * N + 4);
        }
        const unsigned* Asb = As[buf];
        const unsigned* Bsb = Bs[buf];
        MMA_TILE_COMPUTE(Asb, Bsb)
        if (kt + 1 < nt) {
            FILL_A(As[buf ^ 1], av0, av1, 1.f);
            FILL_B(Bs[buf ^ 1], bv0, bv1);
        }
        __syncthreads();
        buf ^= 1;
    }
#pragma unroll
    for (int mt = 0; mt < 4; mt++) {
#pragma unroll
        for (int nt2 = 0; nt2 < 4; nt2++) {
            int r0 = m0 + wm + mt * 16 + g;
            int c = n0 + wn + nt2 * 8 + 2 * tg;
            float2 v0 = make_float2(acc[mt][nt2][0], acc[mt][nt2][1]);
            float2 v1 = make_float2(acc[mt][nt2][2], acc[mt][nt2][3]);
            if (addsrc) {
                float2 r = *(const float2*)(addsrc + (size_t)r0 * N + c);
                v0.x += r.x; v0.y += r.y;
                float2 r2 = *(const float2*)(addsrc + (size_t)(r0 + 8) * N + c);
                v1.x += r2.x; v1.y += r2.y;
            }
            *(float2*)(C + (size_t)r0 * N + c) = v0;
            *(float2*)(C + (size_t)(r0 + 8) * N + c) = v1;
            if (qkv_mode && c >= (NH + NKV) * D) {
                int kvh = (c - (NH + NKV) * D) >> 6;
                int d = (c - (NH + NKV) * D) & 63;
                unsigned* vp0 = g_vT + ((size_t)kvh * T + r0) * D + d;
                vp0[0] = f2tf(v0.x); vp0[1] = f2tf(v0.y);
                unsigned* vp1 = g_vT + ((size_t)kvh * T + r0 + 8) * D + d;
                vp1[0] = f2tf(v1.x); vp1[1] = f2tf(v1.y);
            }
        }
    }
}

// ------------- MoE up-projections mega-GEMM (z = 0..17) ---------------------
__global__ __launch_bounds__(256)
void moe_proj_tf32(const float* __restrict__ shg, const float* __restrict__ shu,
                   const float* __restrict__ wgate, const float* __restrict__ wup) {
    int z = blockIdx.z;
    int m0 = blockIdx.y * 128;
    int cnt, obase;
    const float* B;
    float* Cbuf;
    bool gathered;
    if (z < 2) {
        B = z ? shu : shg;
        Cbuf = z ? g_bufB : g_bufA;
        cnt = T; obase = 0; gathered = false;
    } else {
        int e = (z - 2) >> 1, kind = (z - 2) & 1;
        cnt = g_count[e];
        if (m0 >= cnt) return;
        B = (kind ? wup : wgate) + (size_t)e * H * F;
        Cbuf = kind ? g_bufD : g_bufC;
        obase = g_base[e]; gathered = true;
    }
    int n0 = blockIdx.x * 128;
    __shared__ unsigned As[2][KT * SMS];
    __shared__ unsigned Bs[2][KT * SMS];
    __shared__ int srcrow[128];
    int tid = threadIdx.x;
    if (tid < 128) {
        int mm = m0 + tid;
        srcrow[tid] = gathered ? ((mm < cnt) ? g_perm[obase + mm] : -1) : mm;
    }
    __syncthreads();
    int warp = tid >> 5, lane = tid & 31;
    int g = lane >> 2, tg = lane & 3;
    int wm = (warp >> 2) * 64, wn = (warp & 3) * 32;
    int arow = tid >> 1, acol = (tid & 1) * 8;
    int bk = tid >> 4, bn = (tid & 15) * 8;
    int tok = srcrow[arow];
    float gsc = gathered ? ((tok >= 0) ? g_gate[tok] : 0.f) : 1.f;
    const float* Ap = g_h2 + (size_t)((tok >= 0) ? tok : 0) * H + acol;
    const float* Bp = B + (size_t)bk * F + n0 + bn;
    float acc[4][4][4] = {};

    float4 av0 = *(const float4*)Ap, av1 = *(const float4*)(Ap + 4);
    float4 bv0 = *(const float4*)Bp, bv1 = *(const float4*)(Bp + 4);
    FILL_A(As[0], av0, av1, gsc);
    FILL_B(Bs[0], bv0, bv1);
    __syncthreads();
    int nt = H / KT;
    int buf = 0;
    for (int kt = 0; kt < nt; kt++) {
        if (kt + 1 < nt) {
            av0 = *(const float4*)(Ap + (kt + 1) * KT);
            av1 = *(const float4*)(Ap + (kt + 1) * KT + 4);
            bv0 = *(const float4*)(Bp + (size_t)(kt + 1) * KT * F);
            bv1 = *(const float4*)(Bp + (size_t)(kt + 1) * KT * F + 4);
        }
        const unsigned* Asb = As[buf];
        const unsigned* Bsb = Bs[buf];
        MMA_TILE_COMPUTE(Asb, Bsb)
        if (kt + 1 < nt) {
            FILL_A(As[buf ^ 1], av0, av1, gsc);
            FILL_B(Bs[buf ^ 1], bv0, bv1);
        }
        __syncthreads();
        buf ^= 1;
    }
#pragma unroll
    for (int mt = 0; mt < 4; mt++) {
#pragma unroll
        for (int nt2 = 0; nt2 < 4; nt2++) {
            int mi0 = wm + mt * 16 + g;
            int c = n0 + wn + nt2 * 8 + 2 * tg;
            if (m0 + mi0 < cnt)
                *(float2*)(Cbuf + (size_t)(obase + m0 + mi0) * F + c) =
                    make_float2(acc[mt][nt2][0], acc[mt][nt2][1]);
            if (m0 + mi0 + 8 < cnt)
                *(float2*)(Cbuf + (size_t)(obase + m0 + mi0 + 8) * F + c) =
                    make_float2(acc[mt][nt2][2], acc[mt][nt2][3]);
        }
    }
}

// ------------- MoE down-projections mega-GEMM (z = 0..8, silu fused) --------
__global__ __launch_bounds__(256, 2)
void moe_down_tf32(const float* __restrict__ shd, const float* __restrict__ wdown,
                   float* __restrict__ out) {
    int z = blockIdx.z;
    int m0 = blockIdx.y * 128;
    int cnt, abase;
    const float* B;
    const float* Agate;
    const float* Aup;
    float* Dst;
    if (z == 0) {
        cnt = T; abase = 0;
        B = shd; Agate = g_bufA; Aup = g_bufB; Dst = out;
    } else {
        int e = z - 1;
        cnt = g_count[e];
        if (m0 >= cnt) return;
        abase = g_base[e];
        B = wdown + (size_t)e * F * H;
        Agate = g_bufC; Aup = g_bufD; Dst = g_routed;
    }
    int n0 = blockIdx.x * 128;
    __shared__ unsigned As[2][KT * SMS];
    __shared__ unsigned Bs[2][KT * SMS];
    __shared__ int rtok[128];
    int tid = threadIdx.x;
    if (tid < 128) {
        int mm = m0 + tid;
        rtok[tid] = (z == 0) ? mm : ((mm < cnt) ? g_perm[abase + mm] : -1);
    }
    __syncthreads();
    int warp = tid >> 5, lane = tid & 31;
    int g = lane >> 2, tg = lane & 3;
    int wm = (warp >> 2) * 64, wn = (warp & 3) * 32;
    int arow = tid >> 1, acol = (tid & 1) * 8;
    int bk = tid >> 4, bn = (tid & 15) * 8;
    bool arow_ok = (m0 + arow) < cnt;
    float amask = arow_ok ? 1.f : 0.f;
    size_t aoff = (size_t)(abase + (arow_ok ? (m0 + arow) : 0)) * F + acol;
    const float* Apg = Agate + aoff;
    const float* Apu = Aup + aoff;
    const float* Bp = B + (size_t)bk * H + n0 + bn;
    float acc[4][4][4] = {};

    float4 gv0 = *(const float4*)Apg, gv1 = *(const float4*)(Apg + 4);
    float4 uv0 = *(const float4*)Apu, uv1 = *(const float4*)(Apu + 4);
    float4 bv0 = *(const float4*)Bp, bv1 = *(const float4*)(Bp + 4);
    FILL_A_SILU(As[0], gv0, gv1, uv0, uv1, amask);
    FILL_B(Bs[0], bv0, bv1);
    __syncthreads();
    int nt = F / KT;
    int buf = 0;
    for (int kt = 0; kt < nt; kt++) {
        if (kt + 1 < nt) {
            gv0 = *(const float4*)(Apg + (kt + 1) * KT);
            gv1 = *(const float4*)(Apg + (kt + 1) * KT + 4);
            uv0 = *(const float4*)(Apu + (kt + 1) * KT);
            uv1 = *(const float4*)(Apu + (kt + 1) * KT + 4);
            bv0 = *(const float4*)(Bp + (size_t)(kt + 1) * KT * H);
            bv1 = *(const float4*)(Bp + (size_t)(kt + 1) * KT * H + 4);
        }
        const unsigned* Asb = As[buf];
        const unsigned* Bsb = Bs[buf];
        MMA_TILE_COMPUTE(Asb, Bsb)
        if (kt + 1 < nt) {
            FILL_A_SILU(As[buf ^ 1], gv0, gv1, uv0, uv1, amask);
            FILL_B(Bs[buf ^ 1], bv0, bv1);
        }
        __syncthreads();
        buf ^= 1;
    }
#pragma unroll
    for (int mt = 0; mt < 4; mt++) {
#pragma unroll
        for (int nt2 = 0; nt2 < 4; nt2++) {
            int mi0 = wm + mt * 16 + g;
            int c = n0 + wn + nt2 * 8 + 2 * tg;
            if (m0 + mi0 < cnt) {
                int t = rtok[mi0];
                *(float2*)(Dst + (size_t)t * H + c) =
                    make_float2(acc[mt][nt2][0], acc[mt][nt2][1]);
            }
            if (m0 + mi0 + 8 < cnt) {
                int t = rtok[mi0 + 8];
                *(float2*)(Dst + (size_t)t * H + c) =
                    make_float2(acc[mt][nt2][2], acc[mt][nt2][3]);
            }
        }
    }
}

// ---------------- rope + rms + COALESCED transpose (q,k only) ----------------
__global__ void rope_rms_kernel() {
    int t0 = blockIdx.x * 32;
    int h = blockIdx.y;
    int tid = threadIdx.x;
    const float* src;
    unsigned* dstT;
    if (h < NH) {
        src = g_qkv + h * D;
        dstT = g_qT + (size_t)h * D * T;
    } else {
        src = g_qkv + NH * D + (h - NH) * D;
        dstT = g_kT + (size_t)(h - NH) * D * T;
    }
    __shared__ float rows[32][65];
    __shared__ float psum[32][8];
#pragma unroll
    for (int i = 0; i < 8; i++) {
        int e = tid + i * 256;
        int tl = e >> 6, d = e & 63;
        rows[tl][d] = src[(size_t)(t0 + tl) * QKV_N + d];
    }
    __syncthreads();
    int tl = tid >> 3;
    int dbase = (tid & 7) * 8;
    float vals[8];
    float sq = 0.f;
#pragma unroll
    for (int j = 0; j < 8; j++) {
        int d = dbase + j;
        int i = d & 31;
        float2 cspair = g_cs[(t0 + tl) * 32 + i];
        float x1 = rows[tl][i], x2 = rows[tl][i + 32];
        float val = (d < 32) ? (x1 * cspair.x - x2 * cspair.y)
                             : (x2 * cspair.x + x1 * cspair.y);
        vals[j] = val;
        sq += val * val;
    }
    psum[tl][tid & 7] = sq;
    __syncthreads();
    float tot = 0.f;
#pragma unroll
    for (int k = 0; k < 8; k++) tot += psum[tl][k];
    float r = rsqrtf(tot / (float)D + EPS);
#pragma unroll
    for (int j = 0; j < 8; j++) rows[tl][dbase + j] = vals[j] * r;
    __syncthreads();
#pragma unroll
    for (int i = 0; i < 8; i++) {
        int e = tid + i * 256;
        int d = e >> 5, tcol = e & 31;
        dstT[(size_t)d * T + t0 + tcol] = f2tf(rows[tcol][d]);
    }
}

// ==== flash attention: BM=64, cp.async, P via register shuffles (no Ps) ======
#define AS 72
__global__ __launch_bounds__(128)
void attn_tc() {
    extern __shared__ unsigned usmem[];
    unsigned* Ks0 = usmem;
    unsigned* Ks1 = usmem + 64 * AS;
    unsigned* Vs0 = usmem + 2 * 64 * AS;
    unsigned* Vs1 = usmem + 3 * 64 * AS;
    int qt = (int)gridDim.x - 1 - (int)blockIdx.x;
    int head = blockIdx.y;
    int kvh = head >> 2;
    int tid = threadIdx.x, warp = tid >> 5, lane = tid & 31;
    int g = lane >> 2, tg = lane & 3;
    int q0 = qt * 64;
    int wq = warp * 16;

    const unsigned* ksrc = g_kT + (size_t)kvh * D * T;
    const unsigned* vsrc = g_vT + (size_t)kvh * T * D;

    // stage Q tile into Ks0, lift fragments
    {
        const unsigned* qsrc = g_qT + (size_t)head * D * T + q0;
        for (int e4 = tid; e4 < 64 * 16; e4 += 128) {
            int d = e4 >> 4, r4 = (e4 & 15) * 4;
            uint4 v = *(const uint4*)(qsrc + (size_t)d * T + r4);
            *(uint4*)&Ks0[d * AS + r4] = v;
        }
    }
    __syncthreads();
    unsigned qf[8][4];
#pragma unroll
    for (int kc = 0; kc < 8; kc++) {
        qf[kc][0] = Ks0[(kc * 8 + tg) * AS + wq + g];
        qf[kc][1] = Ks0[(kc * 8 + tg) * AS + wq + g + 8];
        qf[kc][2] = Ks0[(kc * 8 + tg + 4) * AS + wq + g];
        qf[kc][3] = Ks0[(kc * 8 + tg + 4) * AS + wq + g + 8];
    }
    __syncthreads();

    int r0 = q0 + wq + g, r1 = r0 + 8;
    float m0 = -INFINITY, m1 = -INFINITY, l0 = 0.f, l1 = 0.f;
    float accO[8][4] = {};

    {
        for (int e4 = tid; e4 < 64 * 16; e4 += 128) {
            int d = e4 >> 4, c4 = (e4 & 15) * 4;
            cp16((unsigned)__cvta_generic_to_shared(&Ks0[d * AS + c4]),
                 ksrc + (size_t)d * T + c4);
        }
        for (int e4 = tid; e4 < 64 * 16; e4 += 128) {
            int c = e4 >> 4, d4 = (e4 & 15) * 4;
            cp16((unsigned)__cvta_generic_to_shared(&Vs0[c * AS + d4]),
                 vsrc + (size_t)c * D + d4);
        }
        CP_COMMIT();
    }

    int src0 = (lane & 28) | (tg >> 1);   // lane with tg' = tg>>1
    int src1 = src0 + 2;                   // lane with tg' = tg>>1 + 2
    bool odd = (tg & 1);

    int buf = 0;
    for (int j0 = 0; j0 <= qt; j0++) {
        int k0 = j0 * 64;
        CP_WAIT0();
        __syncthreads();
        if (j0 < qt) {
            unsigned* Kn = buf ? Ks0 : Ks1;
            unsigned* Vn = buf ? Vs0 : Vs1;
            int kn = k0 + 64;
            for (int e4 = tid; e4 < 64 * 16; e4 += 128) {
                int d = e4 >> 4, c4 = (e4 & 15) * 4;
                cp16((unsigned)__cvta_generic_to_shared(&Kn[d * AS + c4]),
                     ksrc + (size_t)d * T + kn + c4);
            }
            for (int e4 = tid; e4 < 64 * 16; e4 += 128) {
                int c = e4 >> 4, d4 = (e4 & 15) * 4;
                cp16((unsigned)__cvta_generic_to_shared(&Vn[c * AS + d4]),
                     vsrc + (size_t)(kn + c) * D + d4);
            }
            CP_COMMIT();
        }
        const unsigned* Kb = buf ? Ks1 : Ks0;
        const unsigned* Vb = buf ? Vs1 : Vs0;
        // S = Q K^T
        float sc[8][4] = {};
#pragma unroll
        for (int kc = 0; kc < 8; kc++) {
            unsigned bfr[8][2];
#pragma unroll
            for (int n = 0; n < 8; n++) {
                bfr[n][0] = Kb[(kc * 8 + tg) * AS + n * 8 + g];
                bfr[n][1] = Kb[(kc * 8 + tg + 4) * AS + n * 8 + g];
            }
#pragma unroll
            for (int n = 0; n < 8; n++) mma_tf32(sc[n], qf[kc], bfr[n]);
        }
        // mask + scale + row max
        float mx0 = -INFINITY, mx1 = -INFINITY;
#pragma unroll
        for (int n = 0; n < 8; n++) {
            int c0 = k0 + n * 8 + 2 * tg;
            float s0 = (c0 <= r0) ? sc[n][0] * ATT_SCALE : -INFINITY;
            float s1 = (c0 + 1 <= r0) ? sc[n][1] * ATT_SCALE : -INFINITY;
            float s2 = (c0 <= r1) ? sc[n][2] * ATT_SCALE : -INFINITY;
            float s3 = (c0 + 1 <= r1) ? sc[n][3] * ATT_SCALE : -INFINITY;
            sc[n][0] = s0; sc[n][1] = s1; sc[n][2] = s2; sc[n][3] = s3;
            mx0 = fmaxf(mx0, fmaxf(s0, s1));
            mx1 = fmaxf(mx1, fmaxf(s2, s3));
        }
        mx0 = fmaxf(mx0, __shfl_xor_sync(0xffffffffu, mx0, 1));
        mx0 = fmaxf(mx0, __shfl_xor_sync(0xffffffffu, mx0, 2));
        mx1 = fmaxf(mx1, __shfl_xor_sync(0xffffffffu, mx1, 1));
        mx1 = fmaxf(mx1, __shfl_xor_sync(0xffffffffu, mx1, 2));
        float nm0 = fmaxf(m0, mx0), nm1 = fmaxf(m1, mx1);
        float corr0 = __expf(m0 - nm0), corr1 = __expf(m1 - nm1);
        m0 = nm0; m1 = nm1;
        // exp in-place, accumulate row sums
        float rs0 = 0.f, rs1 = 0.f;
#pragma unroll
        for (int n = 0; n < 8; n++) {
            float p0 = __expf(sc[n][0] - nm0);
            float p1 = __expf(sc[n][1] - nm0);
            float p2 = __expf(sc[n][2] - nm1);
            float p3 = __expf(sc[n][3] - nm1);
            rs0 += p0 + p1; rs1 += p2 + p3;
            sc[n][0] = p0; sc[n][1] = p1; sc[n][2] = p2; sc[n][3] = p3;
        }
        rs0 += __shfl_xor_sync(0xffffffffu, rs0, 1);
        rs0 += __shfl_xor_sync(0xffffffffu, rs0, 2);
        rs1 += __shfl_xor_sync(0xffffffffu, rs1, 1);
        rs1 += __shfl_xor_sync(0xffffffffu, rs1, 2);
        l0 = l0 * corr0 + rs0;
        l1 = l1 * corr1 + rs1;
#pragma unroll
        for (int n = 0; n < 8; n++) {
            accO[n][0] *= corr0; accO[n][1] *= corr0;
            accO[n][2] *= corr1; accO[n][3] *= corr1;
        }
        // O += P V  — P A-fragments built via shuffles from S C-fragments
#pragma unroll
        for (int kc = 0; kc < 8; kc++) {
            float a0e = __shfl_sync(0xffffffffu, sc[kc][0], src0);
            float a0o = __shfl_sync(0xffffffffu, sc[kc][1], src0);
            float a1e = __shfl_sync(0xffffffffu, sc[kc][2], src0);
            float a1o = __shfl_sync(0xffffffffu, sc[kc][3], src0);
            float a2e = __shfl_sync(0xffffffffu, sc[kc][0], src1);
            float a2o = __shfl_sync(0xffffffffu, sc[kc][1], src1);
            float a3e = __shfl_sync(0xffffffffu, sc[kc][2], src1);
            float a3o = __shfl_sync(0xffffffffu, sc[kc][3], src1);
            unsigned af[4];
            af[0] = f2tf(odd ? a0o : a0e);   // P[row g   ][key kc*8+tg  ]
            af[1] = f2tf(odd ? a1o : a1e);   // P[row g+8 ][key kc*8+tg  ]
            af[2] = f2tf(odd ? a2o : a2e);   // P[row g   ][key kc*8+tg+4]
            af[3] = f2tf(odd ? a3o : a3e);   // P[row g+8 ][key kc*8+tg+4]
#pragma unroll
            for (int n = 0; n < 8; n++) {
                unsigned bfr2[2];
                bfr2[0] = Vb[(kc * 8 + tg) * AS + n * 8 + g];
                bfr2[1] = Vb[(kc * 8 + tg + 4) * AS + n * 8 + g];
                mma_tf32(accO[n], af, bfr2);
            }
        }
        buf ^= 1;
    }
    float inv0 = 1.f / l0, inv1 = 1.f / l1;
#pragma unroll
    for (int n = 0; n < 8; n++) {
        int c = head * D + n * 8 + 2 * tg;
        *(float2*)&g_ao[(size_t)r0 * (NH * D) + c] =
            make_float2(accO[n][0] * inv0, accO[n][1] * inv0);
        *(float2*)&g_ao[(size_t)r1 * (NH * D) + c] =
            make_float2(accO[n][2] * inv1, accO[n][3] * inv1);
    }
}

// ---------------- launch ------------------------------------------------------
extern "C" void kernel_launch(void* const* d_in, const int* in_sizes, int n_in,
                              void* d_out, int out_size) {
    const int* pos = (const int*)d_in[0];
    const float* hidden = (const float*)d_in[1];
    const float* ln1 = (const float*)d_in[2];
    const float* ln2 = (const float*)d_in[3];
    const float* wqkv = (const float*)d_in[4];
    const float* wo = (const float*)d_in[5];
    const float* rw = (const float*)d_in[6];
    const float* wgate = (const float*)d_in[7];
    const float* wup = (const float*)d_in[8];
    const float* wdown = (const float*)d_in[9];
    const float* shg = (const float*)d_in[10];
    const float* shu = (const float*)d_in[11];
    const float* shd = (const float*)d_in[12];
    float* out = (float*)d_out;
    float* resid = out + (size_t)T * H;

    float *p_h1, *p_h2, *p_qkv, *p_ao;
    cudaGetSymbolAddress((void**)&p_h1, g_h1);
    cudaGetSymbolAddress((void**)&p_h2, g_h2);
    cudaGetSymbolAddress((void**)&p_qkv, g_qkv);
    cudaGetSymbolAddress((void**)&p_ao, g_ao);

    static int attn_smem_set = 0;
    const int ATTN_SMEM = 4 * 64 * AS * 4;   // 73728 B -> 3 CTA/SM
    if (!attn_smem_set) {
        cudaFuncSetAttribute(attn_tc, cudaFuncAttributeMaxDynamicSharedMemorySize, ATTN_SMEM);
        attn_smem_set = 1;
    }

    pre_kernel<<<T + 256, 256>>>(pos, hidden, ln1, p_h1);
    gemm_tf32<<<dim3(QKV_N / 128, T / 128), 256>>>(p_h1, wqkv, p_qkv, T, QKV_N, H, nullptr, 1);
    rope_rms_kernel<<<dim3(T / 32, NH + NKV), 256>>>();
    attn_tc<<<dim3(T / 64, NH), 128, ATTN_SMEM>>>();
    gemm_tf32<<<dim3(H / 128, T / 128), 256>>>(p_ao, wo, resid, T, H, NH * D, hidden, 0);
    rmsnorm_router_kernel<<<T, 256>>>(resid, ln2, rw, p_h2);
    scan_scatter_kernel<<<1, 256>>>();
    moe_proj_tf32<<<dim3(F / 128, T / 128, 2 + 2 * E), 256>>>(shg, shu, wgate, wup);
    moe_down_tf32<<<dim3(H / 128, T / 128, 1 + E), 256>>>(shd, wdown, out);
    add_routed_kernel<<<(T * H) / 1024, 256>>>(out);
    (void)in_sizes; (void)n_in; (void)out_size;
}